// round 2
// baseline (speedup 1.0000x reference)
#include <cuda_runtime.h>

#define NN 100000
#define NE 1600000
#define NG 512

// ---------------- scratch (device globals; no allocations allowed) ----------
__device__ float g_deg[NN];          // 1/deg  (deg = in-degree + 1)
__device__ float g_dinv[NN];         // rsqrt(deg)
__device__ int   g_cnti[NN];         // int in-degree counts
__device__ int   g_cursor[NN];       // CSR fill cursors
__device__ int   g_rowstart[NN + 1]; // CSR row offsets
__device__ float2 g_csr[NE];         // per-edge (norm, src-as-int)
__device__ float g_agg1[NN * 80];    // aggregated x (78 used, padded to 80)
__device__ float g_h1[NN * 128];     // relu(gcn1)
__device__ float g_agg2[NN * 128];   // aggregated h1
__device__ float g_sums[NG * 256];   // per-graph sums of h2
__device__ float g_cnt[NG];          // per-graph node counts
__device__ float g_ptab[25 * 8 * 64];// precomputed emb@conv_w table [tok][k][o]
__device__ float g_prot[NG * 64];    // protein features after maxpool

// ---------------- zero + degree count ----------------------------------------
__global__ void k_zero() {
    int t = blockIdx.x * blockDim.x + threadIdx.x;
    int stride = gridDim.x * blockDim.x;
    for (int i = t; i < NN; i += stride) { g_cnti[i] = 0; g_cursor[i] = 0; }
    for (int i = t; i < NG * 256; i += stride) g_sums[i] = 0.f;
    for (int i = t; i < NG; i += stride) g_cnt[i] = 0.f;
}

__global__ void k_count(const int* __restrict__ dst) {
    int t = blockIdx.x * blockDim.x + threadIdx.x;
    if (t < NE) atomicAdd(&g_cnti[dst[t]], 1);
}

// one-block prefix scan over NN counts; also computes 1/deg, rsqrt(deg),
// and the per-graph node counts.
__global__ __launch_bounds__(1024) void k_scan(const int* __restrict__ batch) {
    __shared__ int ssum[1024];
    const int CH = (NN + 1023) / 1024;   // 98
    int t = threadIdx.x;
    int base = t * CH;
    int sum = 0;
    for (int i = 0; i < CH; i++) {
        int j = base + i;
        if (j < NN) sum += g_cnti[j];
    }
    ssum[t] = sum;
    __syncthreads();
    // Hillis-Steele inclusive scan
    for (int off = 1; off < 1024; off <<= 1) {
        int v = (t >= off) ? ssum[t - off] : 0;
        __syncthreads();
        ssum[t] += v;
        __syncthreads();
    }
    int run = ssum[t] - sum;             // exclusive prefix
    for (int i = 0; i < CH; i++) {
        int j = base + i;
        if (j < NN) {
            int c = g_cnti[j];
            g_rowstart[j] = run;
            run += c;
            float d = (float)c + 1.0f;
            g_deg[j] = 1.0f / d;
            g_dinv[j] = rsqrtf(d);
            atomicAdd(&g_cnt[batch[j]], 1.0f);
        }
    }
    if (t == 1023) g_rowstart[NN] = run;
}

// fill CSR: slot per edge under dst, store (norm, src)
__global__ void k_fill(const int* __restrict__ src, const int* __restrict__ dst) {
    int t = blockIdx.x * blockDim.x + threadIdx.x;
    if (t < NE) {
        int s = src[t], d = dst[t];
        int pos = g_rowstart[d] + atomicAdd(&g_cursor[d], 1);
        g_csr[pos] = make_float2(g_dinv[s] * g_dinv[d], __int_as_float(s));
    }
}

// ---------------- gather-reduce, layer 1 (78 floats) -------------------------
// warp per node; lanes 0..18 own float4 chunks, lane 19 the tail float2.
__global__ __launch_bounds__(256) void k_gather1(const float* __restrict__ x) {
    int w = (blockIdx.x * blockDim.x + threadIdx.x) >> 5;
    int lane = threadIdx.x & 31;
    if (w >= NN) return;
    int n = w;
    float4 acc = make_float4(0.f, 0.f, 0.f, 0.f);
    float inv = g_deg[n];
    if (lane < 19) {
        const float2* xp = (const float2*)(x + (long)n * 78 + lane * 4);
        float2 a = xp[0], b = xp[1];
        acc = make_float4(a.x * inv, a.y * inv, b.x * inv, b.y * inv);
    } else if (lane == 19) {
        float2 a = *(const float2*)(x + (long)n * 78 + 76);
        acc.x = a.x * inv; acc.y = a.y * inv;
    }
    int beg = g_rowstart[n], end = g_rowstart[n + 1];
    for (int e = beg; e < end; e += 32) {
        float2 meta = (e + lane < end) ? g_csr[e + lane] : make_float2(0.f, 0.f);
        int cnt = min(32, end - e);
        for (int i = 0; i < cnt; i++) {
            float nrm = __shfl_sync(0xffffffffu, meta.x, i);
            int s = __shfl_sync(0xffffffffu, __float_as_int(meta.y), i);
            if (lane < 19) {
                const float2* xp = (const float2*)(x + (long)s * 78 + lane * 4);
                float2 a = xp[0], b = xp[1];
                acc.x += a.x * nrm; acc.y += a.y * nrm;
                acc.z += b.x * nrm; acc.w += b.y * nrm;
            } else if (lane == 19) {
                float2 a = *(const float2*)(x + (long)s * 78 + 76);
                acc.x += a.x * nrm; acc.y += a.y * nrm;
            }
        }
    }
    if (lane < 19)
        *(float4*)(g_agg1 + (long)n * 80 + lane * 4) = acc;
    else if (lane == 19)
        *(float2*)(g_agg1 + (long)n * 80 + 76) = make_float2(acc.x, acc.y);
}

// ---------------- gather-reduce, layer 2 (128 floats) ------------------------
__global__ __launch_bounds__(256) void k_gather2() {
    int w = (blockIdx.x * blockDim.x + threadIdx.x) >> 5;
    int lane = threadIdx.x & 31;
    if (w >= NN) return;
    int n = w;
    float inv = g_deg[n];
    float4 acc = ((const float4*)(g_h1 + (long)n * 128))[lane];
    acc.x *= inv; acc.y *= inv; acc.z *= inv; acc.w *= inv;
    int beg = g_rowstart[n], end = g_rowstart[n + 1];
    for (int e = beg; e < end; e += 32) {
        float2 meta = (e + lane < end) ? g_csr[e + lane] : make_float2(0.f, 0.f);
        int cnt = min(32, end - e);
        for (int i = 0; i < cnt; i++) {
            float nrm = __shfl_sync(0xffffffffu, meta.x, i);
            int s = __shfl_sync(0xffffffffu, __float_as_int(meta.y), i);
            float4 v = ((const float4*)(g_h1 + (long)s * 128))[lane];
            acc.x += v.x * nrm; acc.y += v.y * nrm;
            acc.z += v.z * nrm; acc.w += v.w * nrm;
        }
    }
    ((float4*)(g_agg2 + (long)n * 128))[lane] = acc;
}

// ---------------- GEMM1: h1 = relu(agg1 @ W1 + b1), [NN,78]@[78,128] --------
__global__ __launch_bounds__(256) void k_gemm1(const float* __restrict__ W1,
                                               const float* __restrict__ b1) {
    __shared__ float sA[128 * 41];
    __shared__ float sB[40 * 128];
    int tid = threadIdx.x;
    int r0 = blockIdx.x * 128;
    int cx = tid & 7, ry = tid >> 3;
    float acc[4][16];
#pragma unroll
    for (int i = 0; i < 4; i++)
#pragma unroll
        for (int j = 0; j < 16; j++) acc[i][j] = 0.f;

#pragma unroll 1
    for (int kc = 0; kc < 80; kc += 40) {
        __syncthreads();
        for (int idx = tid; idx < 40 * 128; idx += 256) {
            int k = idx >> 7, c = idx & 127;
            int gk = kc + k;
            sB[idx] = (gk < 78) ? W1[gk * 128 + c] : 0.f;
        }
        for (int idx = tid; idx < 128 * 40; idx += 256) {
            int r = idx / 40, k = idx - r * 40;
            int row = r0 + r;
            sA[r * 41 + k] = (row < NN) ? g_agg1[(long)row * 80 + kc + k] : 0.f;
        }
        __syncthreads();
#pragma unroll 8
        for (int k = 0; k < 40; k++) {
            float a[4];
#pragma unroll
            for (int i = 0; i < 4; i++) a[i] = sA[(ry * 4 + i) * 41 + k];
            const float4* B4 = (const float4*)(sB + k * 128);
#pragma unroll
            for (int q = 0; q < 4; q++) {
                float4 b = B4[cx * 4 + q];
#pragma unroll
                for (int i = 0; i < 4; i++) {
                    acc[i][q * 4 + 0] += a[i] * b.x;
                    acc[i][q * 4 + 1] += a[i] * b.y;
                    acc[i][q * 4 + 2] += a[i] * b.z;
                    acc[i][q * 4 + 3] += a[i] * b.w;
                }
            }
        }
    }
    int colb = cx * 16;
#pragma unroll
    for (int i = 0; i < 4; i++) {
        int row = r0 + ry * 4 + i;
        if (row < NN) {
#pragma unroll
            for (int q = 0; q < 4; q++) {
                float4 v;
                v.x = fmaxf(acc[i][q * 4 + 0] + b1[colb + q * 4 + 0], 0.f);
                v.y = fmaxf(acc[i][q * 4 + 1] + b1[colb + q * 4 + 1], 0.f);
                v.z = fmaxf(acc[i][q * 4 + 2] + b1[colb + q * 4 + 2], 0.f);
                v.w = fmaxf(acc[i][q * 4 + 3] + b1[colb + q * 4 + 3], 0.f);
                *(float4*)(g_h1 + (long)row * 128 + colb + q * 4) = v;
            }
        }
    }
}

// ---------------- GEMM2 + fused mean-pool epilogue ---------------------------
__global__ __launch_bounds__(256) void k_gemm2(const float* __restrict__ W2,
                                               const float* __restrict__ b2,
                                               const int* __restrict__ batch) {
    __shared__ float sA[128 * 33];
    __shared__ float sB[32 * 128];
    int tid = threadIdx.x;
    int r0 = blockIdx.x * 128;
    int cb = blockIdx.y * 128;
    int cx = tid & 7, ry = tid >> 3;
    float acc[4][16];
#pragma unroll
    for (int i = 0; i < 4; i++)
#pragma unroll
        for (int j = 0; j < 16; j++) acc[i][j] = 0.f;

#pragma unroll 1
    for (int kc = 0; kc < 128; kc += 32) {
        __syncthreads();
        for (int idx = tid; idx < 32 * 128; idx += 256) {
            int k = idx >> 7, c = idx & 127;
            sB[idx] = W2[(kc + k) * 256 + cb + c];
        }
        for (int idx = tid; idx < 128 * 32; idx += 256) {
            int r = idx >> 5, k = idx & 31;
            int row = r0 + r;
            sA[r * 33 + k] = (row < NN) ? g_agg2[(long)row * 128 + kc + k] : 0.f;
        }
        __syncthreads();
#pragma unroll 8
        for (int k = 0; k < 32; k++) {
            float a[4];
#pragma unroll
            for (int i = 0; i < 4; i++) a[i] = sA[(ry * 4 + i) * 33 + k];
            const float4* B4 = (const float4*)(sB + k * 128);
#pragma unroll
            for (int q = 0; q < 4; q++) {
                float4 b = B4[cx * 4 + q];
#pragma unroll
                for (int i = 0; i < 4; i++) {
                    acc[i][q * 4 + 0] += a[i] * b.x;
                    acc[i][q * 4 + 1] += a[i] * b.y;
                    acc[i][q * 4 + 2] += a[i] * b.z;
                    acc[i][q * 4 + 3] += a[i] * b.w;
                }
            }
        }
    }
    int colb = cx * 16;
#pragma unroll
    for (int i = 0; i < 4; i++) {
        int row = r0 + ry * 4 + i;
        if (row < NN) {
            int g = batch[row];
            float* base = g_sums + g * 256 + cb + colb;
#pragma unroll
            for (int q = 0; q < 4; q++) {
                float vx = fmaxf(acc[i][q * 4 + 0] + b2[cb + colb + q * 4 + 0], 0.f);
                float vy = fmaxf(acc[i][q * 4 + 1] + b2[cb + colb + q * 4 + 1], 0.f);
                float vz = fmaxf(acc[i][q * 4 + 2] + b2[cb + colb + q * 4 + 2], 0.f);
                float vw = fmaxf(acc[i][q * 4 + 3] + b2[cb + colb + q * 4 + 3], 0.f);
                asm volatile("red.global.add.v4.f32 [%0], {%1,%2,%3,%4};"
                             :: "l"(base + q * 4), "f"(vx), "f"(vy), "f"(vz), "f"(vw)
                             : "memory");
            }
        }
    }
}

// ---------------- protein path -----------------------------------------------
__global__ void k_ptable(const float* __restrict__ emb,
                         const float* __restrict__ conv_w) {
    int idx = blockIdx.x * blockDim.x + threadIdx.x;
    if (idx < 25 * 8 * 64) {
        int o = idx & 63;
        int k = (idx >> 6) & 7;
        int tok = idx >> 9;
        float s = 0.f;
#pragma unroll 4
        for (int i = 0; i < 128; i++)
            s += emb[tok * 128 + i] * conv_w[o * 1024 + i * 8 + k];
        g_ptab[tok * 512 + k * 64 + o] = s;
    }
}

__global__ __launch_bounds__(256) void k_conv(const int* __restrict__ seq,
                                              const float* __restrict__ conv_b) {
    __shared__ float stab[25 * 8 * 32];
    __shared__ int sseq[1024];
    __shared__ float sred[256];
    int tid = threadIdx.x;
    int b = blockIdx.x;
    int co = blockIdx.y * 32;

    for (int idx = tid; idx < 1024; idx += 256) sseq[idx] = seq[b * 1024 + idx];
    for (int idx = tid; idx < 25 * 8 * 32; idx += 256) {
        int oc = idx & 31;
        int kk = (idx >> 5) & 7;
        int tok = idx >> 8;
        stab[idx] = g_ptab[tok * 512 + kk * 64 + co + oc];
    }
    __syncthreads();

    int oc = tid & 31;
    int l0 = tid >> 5;
    float m = -1e30f;
    for (int l = l0; l < 1017; l += 8) {
        float s = 0.f;
#pragma unroll
        for (int k = 0; k < 8; k++)
            s += stab[(sseq[l + k] * 8 + k) * 32 + oc];
        m = fmaxf(m, s);
    }
    sred[tid] = m;
    __syncthreads();
    if (tid < 32) {
        float mm = sred[tid];
#pragma unroll
        for (int g = 1; g < 8; g++) mm = fmaxf(mm, sred[g * 32 + tid]);
        g_prot[b * 64 + co + tid] = fmaxf(mm + conv_b[co + tid], 0.f);
    }
}

// ---------------- final MLP ---------------------------------------------------
__global__ __launch_bounds__(256) void k_final(const float* __restrict__ fc1_w,
                                               const float* __restrict__ fc1_b,
                                               const float* __restrict__ fc2_w,
                                               const float* __restrict__ fc2_b,
                                               float* __restrict__ out) {
    __shared__ float comb[320];
    __shared__ float sred[256];
    int tid = threadIdx.x;
    int b = blockIdx.x;
    float invc = 1.0f / fmaxf(g_cnt[b], 1.0f);
    if (tid < 256) comb[tid] = g_sums[b * 256 + tid] * invc;
    if (tid < 64) comb[256 + tid] = g_prot[b * 64 + tid];
    __syncthreads();

    float part = 0.f;
#pragma unroll
    for (int rep = 0; rep < 2; rep++) {
        int o = tid + rep * 256;
        float acc = fc1_b[o];
#pragma unroll 4
        for (int j = 0; j < 320; j++)
            acc += comb[j] * fc1_w[j * 512 + o];
        part += fmaxf(acc, 0.f) * fc2_w[o];
    }
    sred[tid] = part;
    __syncthreads();
    for (int s = 128; s > 0; s >>= 1) {
        if (tid < s) sred[tid] += sred[tid + s];
        __syncthreads();
    }
    if (tid == 0) out[b] = sred[0] + fc2_b[0];
}

// ---------------- launch ------------------------------------------------------
extern "C" void kernel_launch(void* const* d_in, const int* in_sizes, int n_in,
                              void* d_out, int out_size) {
    const float* x       = (const float*)d_in[0];
    const int*   ei      = (const int*)  d_in[1];   // [2, NE]
    const int*   batch   = (const int*)  d_in[2];
    const int*   seq     = (const int*)  d_in[3];   // [NG, 1024]
    const float* W1      = (const float*)d_in[4];
    const float* b1      = (const float*)d_in[5];
    const float* W2      = (const float*)d_in[6];
    const float* b2      = (const float*)d_in[7];
    const float* emb     = (const float*)d_in[8];
    const float* conv_w  = (const float*)d_in[9];
    const float* conv_b  = (const float*)d_in[10];
    const float* fc1_w   = (const float*)d_in[11];
    const float* fc1_b   = (const float*)d_in[12];
    const float* fc2_w   = (const float*)d_in[13];
    const float* fc2_b   = (const float*)d_in[14];
    float* out = (float*)d_out;

    const int* src = ei;
    const int* dst = ei + NE;

    k_zero<<<512, 256>>>();
    k_count<<<(NE + 255) / 256, 256>>>(dst);
    k_scan<<<1, 1024>>>(batch);
    k_fill<<<(NE + 255) / 256, 256>>>(src, dst);
    k_gather1<<<(NN * 32 + 255) / 256, 256>>>(x);
    k_gemm1<<<(NN + 127) / 128, 256>>>(W1, b1);
    k_gather2<<<(NN * 32 + 255) / 256, 256>>>();
    {
        dim3 grid((NN + 127) / 128, 2);
        k_gemm2<<<grid, 256>>>(W2, b2, batch);
    }
    k_ptable<<<(25 * 8 * 64 + 255) / 256, 256>>>(emb, conv_w);
    {
        dim3 grid(NG, 2);
        k_conv<<<grid, 256>>>(seq, conv_b);
    }
    k_final<<<NG, 256>>>(fc1_w, fc1_b, fc2_w, fc2_b, out);
}

// round 3
// speedup vs baseline: 1.0759x; 1.0759x over previous
#include <cuda_runtime.h>

#define NN 100000
#define NE 1600000
#define NG 512

// ---------------- scratch (device globals; no allocations allowed) ----------
__device__ int   g_cnti[NN];         // int in-degree counts (deg = cnti + 1)
__device__ float g_agg1[NN * 80];    // aggregated x (78 used, padded to 80)
__device__ float g_h1[NN * 128];     // relu(gcn1)
__device__ float g_agg2[NN * 128];   // aggregated h1
__device__ float g_sums[NG * 256];   // per-graph sums of h2
__device__ float g_cnt[NG];          // per-graph node counts
__device__ float g_ptab[25 * 8 * 64];// precomputed emb@conv_w table [tok][k][o]
__device__ float g_prot[NG * 64];    // protein features after maxpool

// ---------------- zero + degree count ----------------------------------------
__global__ void k_zero() {
    int t = blockIdx.x * blockDim.x + threadIdx.x;
    int stride = gridDim.x * blockDim.x;
    for (int i = t; i < NN; i += stride) g_cnti[i] = 0;
    for (int i = t; i < NG * 256; i += stride) g_sums[i] = 0.f;
    for (int i = t; i < NG; i += stride) g_cnt[i] = 0.f;
}

__global__ void k_deg(const int* __restrict__ dst) {
    int t = blockIdx.x * blockDim.x + threadIdx.x;
    if (t < NE) atomicAdd(&g_cnti[dst[t]], 1);
}

// init agg1 with the self-loop term: agg1[i] = x[i] / deg_i; pad cols 78,79 = 0
__global__ void k_init1(const float* __restrict__ x) {
    int t = blockIdx.x * blockDim.x + threadIdx.x;
    if (t < NN * 80) {
        int i = t / 80;
        int j = t - i * 80;
        float inv = 1.0f / ((float)g_cnti[i] + 1.0f);
        g_agg1[t] = (j < 78) ? x[i * 78 + j] * inv : 0.f;
    }
}

// ---------------- edge scatter, layer 1 (78 floats / edge) ------------------
// warp per edge: lanes 0..18 handle float4 chunks, lane 19 the final float2.
// All lanes load edge meta (same-address broadcast) and compute nrm locally.
__global__ void k_scatter1(const float* __restrict__ x,
                           const int* __restrict__ src,
                           const int* __restrict__ dst) {
    int w = (blockIdx.x * blockDim.x + threadIdx.x) >> 5;
    int lane = threadIdx.x & 31;
    int nwarp = (gridDim.x * blockDim.x) >> 5;
    for (int e = w; e < NE; e += nwarp) {
        int s = __ldg(src + e);
        int d = __ldg(dst + e);
        float nrm = rsqrtf((float)__ldg(g_cnti + s) + 1.0f) *
                    rsqrtf((float)__ldg(g_cnti + d) + 1.0f);
        if (lane < 19) {
            // x row byte offset = 312*s + 16*lane -> 8-byte aligned: two float2 loads
            const float2* xp = (const float2*)(x + (long)s * 78 + lane * 4);
            float2 a = xp[0], b = xp[1];
            float* p = g_agg1 + (long)d * 80 + lane * 4;   // 16B aligned
            asm volatile("red.global.add.v4.f32 [%0], {%1,%2,%3,%4};"
                         :: "l"(p), "f"(a.x * nrm), "f"(a.y * nrm),
                            "f"(b.x * nrm), "f"(b.y * nrm) : "memory");
        } else if (lane == 19) {
            float2 a = *(const float2*)(x + (long)s * 78 + 76);
            float* p = g_agg1 + (long)d * 80 + 76;          // 8B aligned
            asm volatile("red.global.add.v2.f32 [%0], {%1,%2};"
                         :: "l"(p), "f"(a.x * nrm), "f"(a.y * nrm) : "memory");
        }
    }
}

// ---------------- GEMM1: h1 = relu(agg1 @ W1 + b1), [NN,78]@[78,128] --------
__global__ __launch_bounds__(256) void k_gemm1(const float* __restrict__ W1,
                                               const float* __restrict__ b1) {
    __shared__ float sA[128 * 41];
    __shared__ float sB[40 * 128];
    int tid = threadIdx.x;
    int r0 = blockIdx.x * 128;
    int cx = tid & 7, ry = tid >> 3;
    float acc[4][16];
#pragma unroll
    for (int i = 0; i < 4; i++)
#pragma unroll
        for (int j = 0; j < 16; j++) acc[i][j] = 0.f;

#pragma unroll 1
    for (int kc = 0; kc < 80; kc += 40) {
        __syncthreads();
        for (int idx = tid; idx < 40 * 128; idx += 256) {
            int k = idx >> 7, c = idx & 127;
            int gk = kc + k;
            sB[idx] = (gk < 78) ? W1[gk * 128 + c] : 0.f;
        }
        for (int idx = tid; idx < 128 * 40; idx += 256) {
            int r = idx / 40, k = idx - r * 40;
            int row = r0 + r;
            sA[r * 41 + k] = (row < NN) ? g_agg1[(long)row * 80 + kc + k] : 0.f;
        }
        __syncthreads();
#pragma unroll 8
        for (int k = 0; k < 40; k++) {
            float a[4];
#pragma unroll
            for (int i = 0; i < 4; i++) a[i] = sA[(ry * 4 + i) * 41 + k];
            const float4* B4 = (const float4*)(sB + k * 128);
#pragma unroll
            for (int q = 0; q < 4; q++) {
                float4 b = B4[cx * 4 + q];
#pragma unroll
                for (int i = 0; i < 4; i++) {
                    acc[i][q * 4 + 0] += a[i] * b.x;
                    acc[i][q * 4 + 1] += a[i] * b.y;
                    acc[i][q * 4 + 2] += a[i] * b.z;
                    acc[i][q * 4 + 3] += a[i] * b.w;
                }
            }
        }
    }
    int colb = cx * 16;
#pragma unroll
    for (int i = 0; i < 4; i++) {
        int row = r0 + ry * 4 + i;
        if (row < NN) {
#pragma unroll
            for (int q = 0; q < 4; q++) {
                float4 v;
                v.x = fmaxf(acc[i][q * 4 + 0] + b1[colb + q * 4 + 0], 0.f);
                v.y = fmaxf(acc[i][q * 4 + 1] + b1[colb + q * 4 + 1], 0.f);
                v.z = fmaxf(acc[i][q * 4 + 2] + b1[colb + q * 4 + 2], 0.f);
                v.w = fmaxf(acc[i][q * 4 + 3] + b1[colb + q * 4 + 3], 0.f);
                *(float4*)(g_h1 + (long)row * 128 + colb + q * 4) = v;
            }
        }
    }
}

// init agg2 = h1 * (1/deg)
__global__ void k_init2() {
    int t = blockIdx.x * blockDim.x + threadIdx.x;   // one float4 per thread
    if (t < NN * 32) {
        int i = t >> 5;
        float inv = 1.0f / ((float)g_cnti[i] + 1.0f);
        float4 v = ((const float4*)g_h1)[t];
        v.x *= inv; v.y *= inv; v.z *= inv; v.w *= inv;
        ((float4*)g_agg2)[t] = v;
    }
}

// ---------------- edge scatter, layer 2 (128 floats / edge) -----------------
__global__ void k_scatter2(const int* __restrict__ src,
                           const int* __restrict__ dst) {
    int w = (blockIdx.x * blockDim.x + threadIdx.x) >> 5;
    int lane = threadIdx.x & 31;
    int nwarp = (gridDim.x * blockDim.x) >> 5;
    for (int e = w; e < NE; e += nwarp) {
        int s = __ldg(src + e);
        int d = __ldg(dst + e);
        float nrm = rsqrtf((float)__ldg(g_cnti + s) + 1.0f) *
                    rsqrtf((float)__ldg(g_cnti + d) + 1.0f);
        float4 v = ((const float4*)(g_h1 + (long)s * 128))[lane];
        float* p = g_agg2 + (long)d * 128 + lane * 4;
        asm volatile("red.global.add.v4.f32 [%0], {%1,%2,%3,%4};"
                     :: "l"(p), "f"(v.x * nrm), "f"(v.y * nrm),
                        "f"(v.z * nrm), "f"(v.w * nrm) : "memory");
    }
}

// ---------------- GEMM2 + fused mean-pool epilogue ---------------------------
__global__ __launch_bounds__(256) void k_gemm2(const float* __restrict__ W2,
                                               const float* __restrict__ b2,
                                               const int* __restrict__ batch) {
    __shared__ float sA[128 * 33];
    __shared__ float sB[32 * 128];
    int tid = threadIdx.x;
    int r0 = blockIdx.x * 128;
    int cb = blockIdx.y * 128;
    int cx = tid & 7, ry = tid >> 3;
    float acc[4][16];
#pragma unroll
    for (int i = 0; i < 4; i++)
#pragma unroll
        for (int j = 0; j < 16; j++) acc[i][j] = 0.f;

#pragma unroll 1
    for (int kc = 0; kc < 128; kc += 32) {
        __syncthreads();
        for (int idx = tid; idx < 32 * 128; idx += 256) {
            int k = idx >> 7, c = idx & 127;
            sB[idx] = W2[(kc + k) * 256 + cb + c];
        }
        for (int idx = tid; idx < 128 * 32; idx += 256) {
            int r = idx >> 5, k = idx & 31;
            int row = r0 + r;
            sA[r * 33 + k] = (row < NN) ? g_agg2[(long)row * 128 + kc + k] : 0.f;
        }
        __syncthreads();
#pragma unroll 8
        for (int k = 0; k < 32; k++) {
            float a[4];
#pragma unroll
            for (int i = 0; i < 4; i++) a[i] = sA[(ry * 4 + i) * 33 + k];
            const float4* B4 = (const float4*)(sB + k * 128);
#pragma unroll
            for (int q = 0; q < 4; q++) {
                float4 b = B4[cx * 4 + q];
#pragma unroll
                for (int i = 0; i < 4; i++) {
                    acc[i][q * 4 + 0] += a[i] * b.x;
                    acc[i][q * 4 + 1] += a[i] * b.y;
                    acc[i][q * 4 + 2] += a[i] * b.z;
                    acc[i][q * 4 + 3] += a[i] * b.w;
                }
            }
        }
    }
    int colb = cx * 16;
#pragma unroll
    for (int i = 0; i < 4; i++) {
        int row = r0 + ry * 4 + i;
        if (row < NN) {
            int g = batch[row];
            float* base = g_sums + g * 256 + cb + colb;
#pragma unroll
            for (int q = 0; q < 4; q++) {
                float vx = fmaxf(acc[i][q * 4 + 0] + b2[cb + colb + q * 4 + 0], 0.f);
                float vy = fmaxf(acc[i][q * 4 + 1] + b2[cb + colb + q * 4 + 1], 0.f);
                float vz = fmaxf(acc[i][q * 4 + 2] + b2[cb + colb + q * 4 + 2], 0.f);
                float vw = fmaxf(acc[i][q * 4 + 3] + b2[cb + colb + q * 4 + 3], 0.f);
                asm volatile("red.global.add.v4.f32 [%0], {%1,%2,%3,%4};"
                             :: "l"(base + q * 4), "f"(vx), "f"(vy), "f"(vz), "f"(vw)
                             : "memory");
            }
        }
    }
}

// ---------------- protein path -----------------------------------------------
__global__ void k_ptable(const float* __restrict__ emb,
                         const float* __restrict__ conv_w) {
    int idx = blockIdx.x * blockDim.x + threadIdx.x;
    if (idx < 25 * 8 * 64) {
        int o = idx & 63;
        int k = (idx >> 6) & 7;
        int tok = idx >> 9;
        float s = 0.f;
#pragma unroll 4
        for (int i = 0; i < 128; i++)
            s += emb[tok * 128 + i] * conv_w[o * 1024 + i * 8 + k];
        g_ptab[tok * 512 + k * 64 + o] = s;
    }
}

// conv1d(k=8) + relu + global max pool via the 25-token table.
// grid (NG, 2): block = one graph x 32 channels, float2-packed (2 ch / lane).
__global__ __launch_bounds__(256) void k_conv(const int* __restrict__ seq,
                                              const float* __restrict__ conv_b) {
    __shared__ float2 stab[25 * 8 * 16];   // [tok][k][chan-pair]
    __shared__ int sseq[1024];
    __shared__ float2 sred[256];
    int tid = threadIdx.x;
    int b = blockIdx.x;
    int co = blockIdx.y * 32;

    for (int idx = tid; idx < 1024; idx += 256) sseq[idx] = seq[b * 1024 + idx];
    for (int idx = tid; idx < 25 * 8 * 16; idx += 256) {
        int p = idx & 15;
        int kk = (idx >> 4) & 7;
        int tok = idx >> 7;
        stab[idx] = make_float2(g_ptab[tok * 512 + kk * 64 + co + 2 * p],
                                g_ptab[tok * 512 + kk * 64 + co + 2 * p + 1]);
    }
    __syncthreads();

    int p = tid & 15;              // channel pair 0..15
    int phase = tid >> 4;          // 0..15
    float2 m = make_float2(-1e30f, -1e30f);
    for (int l = phase; l < 1017; l += 16) {
        float sx = 0.f, sy = 0.f;
#pragma unroll
        for (int k = 0; k < 8; k++) {
            float2 v = stab[(sseq[l + k] * 8 + k) * 16 + p];
            sx += v.x; sy += v.y;
        }
        m.x = fmaxf(m.x, sx);
        m.y = fmaxf(m.y, sy);
    }
    sred[tid] = m;
    __syncthreads();
    if (tid < 16) {
        float2 mm = sred[tid];
#pragma unroll
        for (int g = 1; g < 16; g++) {
            float2 v = sred[g * 16 + tid];
            mm.x = fmaxf(mm.x, v.x);
            mm.y = fmaxf(mm.y, v.y);
        }
        g_prot[b * 64 + co + 2 * tid]     = fmaxf(mm.x + conv_b[co + 2 * tid], 0.f);
        g_prot[b * 64 + co + 2 * tid + 1] = fmaxf(mm.y + conv_b[co + 2 * tid + 1], 0.f);
    }
}

// per-graph node counts (moved off the critical front so scatter1 is launch #4)
__global__ void k_cnt(const int* __restrict__ batch) {
    int t = blockIdx.x * blockDim.x + threadIdx.x;
    if (t < NN) atomicAdd(&g_cnt[batch[t]], 1.0f);
}

// ---------------- final MLP ---------------------------------------------------
__global__ __launch_bounds__(256) void k_final(const float* __restrict__ fc1_w,
                                               const float* __restrict__ fc1_b,
                                               const float* __restrict__ fc2_w,
                                               const float* __restrict__ fc2_b,
                                               float* __restrict__ out) {
    __shared__ float comb[320];
    __shared__ float sred[256];
    int tid = threadIdx.x;
    int b = blockIdx.x;
    float invc = 1.0f / fmaxf(g_cnt[b], 1.0f);
    if (tid < 256) comb[tid] = g_sums[b * 256 + tid] * invc;
    if (tid < 64) comb[256 + tid] = g_prot[b * 64 + tid];
    __syncthreads();

    float part = 0.f;
#pragma unroll
    for (int rep = 0; rep < 2; rep++) {
        int o = tid + rep * 256;
        float acc = fc1_b[o];
#pragma unroll 4
        for (int j = 0; j < 320; j++)
            acc += comb[j] * fc1_w[j * 512 + o];
        part += fmaxf(acc, 0.f) * fc2_w[o];
    }
    sred[tid] = part;
    __syncthreads();
    for (int s = 128; s > 0; s >>= 1) {
        if (tid < s) sred[tid] += sred[tid + s];
        __syncthreads();
    }
    if (tid == 0) out[b] = sred[0] + fc2_b[0];
}

// ---------------- launch ------------------------------------------------------
extern "C" void kernel_launch(void* const* d_in, const int* in_sizes, int n_in,
                              void* d_out, int out_size) {
    const float* x       = (const float*)d_in[0];
    const int*   ei      = (const int*)  d_in[1];   // [2, NE]
    const int*   batch   = (const int*)  d_in[2];
    const int*   seq     = (const int*)  d_in[3];   // [NG, 1024]
    const float* W1      = (const float*)d_in[4];
    const float* b1      = (const float*)d_in[5];
    const float* W2      = (const float*)d_in[6];
    const float* b2      = (const float*)d_in[7];
    const float* emb     = (const float*)d_in[8];
    const float* conv_w  = (const float*)d_in[9];
    const float* conv_b  = (const float*)d_in[10];
    const float* fc1_w   = (const float*)d_in[11];
    const float* fc1_b   = (const float*)d_in[12];
    const float* fc2_w   = (const float*)d_in[13];
    const float* fc2_b   = (const float*)d_in[14];
    float* out = (float*)d_out;

    const int* src = ei;
    const int* dst = ei + NE;

    k_zero<<<512, 256>>>();                                   // 1
    k_deg<<<(NE + 255) / 256, 256>>>(dst);                    // 2
    k_init1<<<(NN * 80 + 255) / 256, 256>>>(x);               // 3
    k_scatter1<<<2048, 256>>>(x, src, dst);                   // 4  <- profiled
    k_gemm1<<<(NN + 127) / 128, 256>>>(W1, b1);               // 5
    k_init2<<<(NN * 32 + 255) / 256, 256>>>();                // 6
    k_scatter2<<<2048, 256>>>(src, dst);                      // 7
    {
        dim3 grid((NN + 127) / 128, 2);
        k_gemm2<<<grid, 256>>>(W2, b2, batch);                // 8
    }
    k_ptable<<<(25 * 8 * 64 + 255) / 256, 256>>>(emb, conv_w);// 9
    {
        dim3 grid(NG, 2);
        k_conv<<<grid, 256>>>(seq, conv_b);                   // 10
    }
    k_cnt<<<(NN + 255) / 256, 256>>>(batch);                  // 11
    k_final<<<NG, 256>>>(fc1_w, fc1_b, fc2_w, fc2_b, out);    // 12
}

// round 4
// speedup vs baseline: 1.1596x; 1.0778x over previous
#include <cuda_runtime.h>

#define NN 100000
#define NE 1600000
#define NG 512

// ---------------- scratch (device globals; no allocations allowed) ----------
__device__ int   g_cnti[NN];         // int in-degree counts (deg = cnti + 1)
__device__ float g_dinv[NN];         // rsqrt(deg)
__device__ float g_inv[NN];          // 1/deg
__device__ float g_agg1[NN * 80];    // aggregated x (78 used, padded to 80)
__device__ float g_h1[NN * 128];     // relu(gcn1)
__device__ float g_agg2[NN * 128];   // aggregated h1
__device__ float g_sums[NG * 256];   // per-graph sums of h2
__device__ float g_cnt[NG];          // per-graph node counts
__device__ float g_ptab[25 * 8 * 64];// precomputed emb@conv_w table [tok][k][o]
__device__ float g_prot[NG * 64];    // protein features after maxpool

// ---------------- zero + degree count ----------------------------------------
__global__ void k_zero() {
    int t = blockIdx.x * blockDim.x + threadIdx.x;
    int stride = gridDim.x * blockDim.x;
    for (int i = t; i < NN; i += stride) g_cnti[i] = 0;
    for (int i = t; i < NG * 256; i += stride) g_sums[i] = 0.f;
    for (int i = t; i < NG; i += stride) g_cnt[i] = 0.f;
}

__global__ void k_deg(const int* __restrict__ dst) {
    int t = blockIdx.x * blockDim.x + threadIdx.x;
    if (t < NE) atomicAdd(&g_cnti[dst[t]], 1);
}

// init agg1 = x / deg (float4 granularity); also store dinv + inv per node.
// NN*20 threads: i = t/20, q = t%20 (row stride 80 floats = 20 float4).
__global__ void k_init1(const float* __restrict__ x) {
    int t = blockIdx.x * blockDim.x + threadIdx.x;
    if (t < NN * 20) {
        int i = t / 20;
        int q = t - i * 20;
        float d = (float)g_cnti[i] + 1.0f;
        float inv = 1.0f / d;
        if (q == 0) {
            g_dinv[i] = rsqrtf(d);
            g_inv[i] = inv;
        }
        float4 v;
        if (q < 19) {
            const float2* xp = (const float2*)(x + (long)i * 78 + q * 4);
            float2 a = xp[0], b = xp[1];
            v = make_float4(a.x * inv, a.y * inv, b.x * inv, b.y * inv);
        } else {
            float2 a = *(const float2*)(x + (long)i * 78 + 76);
            v = make_float4(a.x * inv, a.y * inv, 0.f, 0.f);
        }
        *(float4*)(g_agg1 + (long)i * 80 + q * 4) = v;
    }
}

// ---------------- edge scatter, layer 1 (78 floats / edge) ------------------
// warp per contiguous edge chunk, unrolled x2 for MLP.
// lanes 0..18 handle float4 chunks, lane 19 the final float2.
__global__ void k_scatter1(const float* __restrict__ x,
                           const int* __restrict__ src,
                           const int* __restrict__ dst) {
    const int W = 2048 * 8;                 // total warps
    const int EPW = (NE + W - 1) / W;       // 98
    int w = (blockIdx.x * blockDim.x + threadIdx.x) >> 5;
    int lane = threadIdx.x & 31;
    int e = w * EPW;
    int end = min(e + EPW, NE);

    for (; e + 1 < end; e += 2) {
        int s0 = __ldg(src + e),     d0 = __ldg(dst + e);
        int s1 = __ldg(src + e + 1), d1 = __ldg(dst + e + 1);
        float n0 = __ldg(g_dinv + s0) * __ldg(g_dinv + d0);
        float n1 = __ldg(g_dinv + s1) * __ldg(g_dinv + d1);
        if (lane < 19) {
            const float2* xp0 = (const float2*)(x + (long)s0 * 78 + lane * 4);
            const float2* xp1 = (const float2*)(x + (long)s1 * 78 + lane * 4);
            float2 a0 = xp0[0], b0 = xp0[1];
            float2 a1 = xp1[0], b1 = xp1[1];
            float* p0 = g_agg1 + (long)d0 * 80 + lane * 4;
            float* p1 = g_agg1 + (long)d1 * 80 + lane * 4;
            asm volatile("red.global.add.v4.f32 [%0], {%1,%2,%3,%4};"
                         :: "l"(p0), "f"(a0.x * n0), "f"(a0.y * n0),
                            "f"(b0.x * n0), "f"(b0.y * n0) : "memory");
            asm volatile("red.global.add.v4.f32 [%0], {%1,%2,%3,%4};"
                         :: "l"(p1), "f"(a1.x * n1), "f"(a1.y * n1),
                            "f"(b1.x * n1), "f"(b1.y * n1) : "memory");
        } else if (lane == 19) {
            float2 a0 = *(const float2*)(x + (long)s0 * 78 + 76);
            float2 a1 = *(const float2*)(x + (long)s1 * 78 + 76);
            float* p0 = g_agg1 + (long)d0 * 80 + 76;
            float* p1 = g_agg1 + (long)d1 * 80 + 76;
            asm volatile("red.global.add.v2.f32 [%0], {%1,%2};"
                         :: "l"(p0), "f"(a0.x * n0), "f"(a0.y * n0) : "memory");
            asm volatile("red.global.add.v2.f32 [%0], {%1,%2};"
                         :: "l"(p1), "f"(a1.x * n1), "f"(a1.y * n1) : "memory");
        }
    }
    if (e < end) {
        int s = __ldg(src + e), d = __ldg(dst + e);
        float nrm = __ldg(g_dinv + s) * __ldg(g_dinv + d);
        if (lane < 19) {
            const float2* xp = (const float2*)(x + (long)s * 78 + lane * 4);
            float2 a = xp[0], b = xp[1];
            float* p = g_agg1 + (long)d * 80 + lane * 4;
            asm volatile("red.global.add.v4.f32 [%0], {%1,%2,%3,%4};"
                         :: "l"(p), "f"(a.x * nrm), "f"(a.y * nrm),
                            "f"(b.x * nrm), "f"(b.y * nrm) : "memory");
        } else if (lane == 19) {
            float2 a = *(const float2*)(x + (long)s * 78 + 76);
            float* p = g_agg1 + (long)d * 80 + 76;
            asm volatile("red.global.add.v2.f32 [%0], {%1,%2};"
                         :: "l"(p), "f"(a.x * nrm), "f"(a.y * nrm) : "memory");
        }
    }
}

// ---------------- GEMM1: h1 = relu(agg1 @ W1 + b1), [NN,78]@[78,128] --------
__global__ __launch_bounds__(256) void k_gemm1(const float* __restrict__ W1,
                                               const float* __restrict__ b1) {
    __shared__ float sA[128 * 41];
    __shared__ float sB[40 * 128];
    int tid = threadIdx.x;
    int r0 = blockIdx.x * 128;
    int cx = tid & 7, ry = tid >> 3;
    float acc[4][16];
#pragma unroll
    for (int i = 0; i < 4; i++)
#pragma unroll
        for (int j = 0; j < 16; j++) acc[i][j] = 0.f;

#pragma unroll 1
    for (int kc = 0; kc < 80; kc += 40) {
        __syncthreads();
        for (int idx = tid; idx < 40 * 128; idx += 256) {
            int k = idx >> 7, c = idx & 127;
            int gk = kc + k;
            sB[idx] = (gk < 78) ? W1[gk * 128 + c] : 0.f;
        }
        for (int idx = tid; idx < 128 * 40; idx += 256) {
            int r = idx / 40, k = idx - r * 40;
            int row = r0 + r;
            sA[r * 41 + k] = (row < NN) ? g_agg1[(long)row * 80 + kc + k] : 0.f;
        }
        __syncthreads();
#pragma unroll 8
        for (int k = 0; k < 40; k++) {
            float a[4];
#pragma unroll
            for (int i = 0; i < 4; i++) a[i] = sA[(ry * 4 + i) * 41 + k];
            const float4* B4 = (const float4*)(sB + k * 128);
#pragma unroll
            for (int q = 0; q < 4; q++) {
                float4 b = B4[cx * 4 + q];
#pragma unroll
                for (int i = 0; i < 4; i++) {
                    acc[i][q * 4 + 0] += a[i] * b.x;
                    acc[i][q * 4 + 1] += a[i] * b.y;
                    acc[i][q * 4 + 2] += a[i] * b.z;
                    acc[i][q * 4 + 3] += a[i] * b.w;
                }
            }
        }
    }
    int colb = cx * 16;
#pragma unroll
    for (int i = 0; i < 4; i++) {
        int row = r0 + ry * 4 + i;
        if (row < NN) {
#pragma unroll
            for (int q = 0; q < 4; q++) {
                float4 v;
                v.x = fmaxf(acc[i][q * 4 + 0] + b1[colb + q * 4 + 0], 0.f);
                v.y = fmaxf(acc[i][q * 4 + 1] + b1[colb + q * 4 + 1], 0.f);
                v.z = fmaxf(acc[i][q * 4 + 2] + b1[colb + q * 4 + 2], 0.f);
                v.w = fmaxf(acc[i][q * 4 + 3] + b1[colb + q * 4 + 3], 0.f);
                *(float4*)(g_h1 + (long)row * 128 + colb + q * 4) = v;
            }
        }
    }
}

// init agg2 = h1 * (1/deg), loading precomputed inv
__global__ void k_init2() {
    int t = blockIdx.x * blockDim.x + threadIdx.x;   // one float4 per thread
    if (t < NN * 32) {
        int i = t >> 5;
        float inv = __ldg(g_inv + i);
        float4 v = ((const float4*)g_h1)[t];
        v.x *= inv; v.y *= inv; v.z *= inv; v.w *= inv;
        ((float4*)g_agg2)[t] = v;
    }
}

// ---------------- edge scatter, layer 2 (128 floats / edge) -----------------
__global__ void k_scatter2(const int* __restrict__ src,
                           const int* __restrict__ dst) {
    const int W = 2048 * 8;
    const int EPW = (NE + W - 1) / W;
    int w = (blockIdx.x * blockDim.x + threadIdx.x) >> 5;
    int lane = threadIdx.x & 31;
    int e = w * EPW;
    int end = min(e + EPW, NE);

    for (; e + 1 < end; e += 2) {
        int s0 = __ldg(src + e),     d0 = __ldg(dst + e);
        int s1 = __ldg(src + e + 1), d1 = __ldg(dst + e + 1);
        float n0 = __ldg(g_dinv + s0) * __ldg(g_dinv + d0);
        float n1 = __ldg(g_dinv + s1) * __ldg(g_dinv + d1);
        float4 v0 = ((const float4*)(g_h1 + (long)s0 * 128))[lane];
        float4 v1 = ((const float4*)(g_h1 + (long)s1 * 128))[lane];
        float* p0 = g_agg2 + (long)d0 * 128 + lane * 4;
        float* p1 = g_agg2 + (long)d1 * 128 + lane * 4;
        asm volatile("red.global.add.v4.f32 [%0], {%1,%2,%3,%4};"
                     :: "l"(p0), "f"(v0.x * n0), "f"(v0.y * n0),
                        "f"(v0.z * n0), "f"(v0.w * n0) : "memory");
        asm volatile("red.global.add.v4.f32 [%0], {%1,%2,%3,%4};"
                     :: "l"(p1), "f"(v1.x * n1), "f"(v1.y * n1),
                        "f"(v1.z * n1), "f"(v1.w * n1) : "memory");
    }
    if (e < end) {
        int s = __ldg(src + e), d = __ldg(dst + e);
        float nrm = __ldg(g_dinv + s) * __ldg(g_dinv + d);
        float4 v = ((const float4*)(g_h1 + (long)s * 128))[lane];
        float* p = g_agg2 + (long)d * 128 + lane * 4;
        asm volatile("red.global.add.v4.f32 [%0], {%1,%2,%3,%4};"
                     :: "l"(p), "f"(v.x * nrm), "f"(v.y * nrm),
                        "f"(v.z * nrm), "f"(v.w * nrm) : "memory");
    }
}

// ---------------- GEMM2 + fused mean-pool epilogue ---------------------------
__global__ __launch_bounds__(256) void k_gemm2(const float* __restrict__ W2,
                                               const float* __restrict__ b2,
                                               const int* __restrict__ batch) {
    __shared__ float sA[128 * 33];
    __shared__ float sB[32 * 128];
    int tid = threadIdx.x;
    int r0 = blockIdx.x * 128;
    int cb = blockIdx.y * 128;
    int cx = tid & 7, ry = tid >> 3;
    float acc[4][16];
#pragma unroll
    for (int i = 0; i < 4; i++)
#pragma unroll
        for (int j = 0; j < 16; j++) acc[i][j] = 0.f;

#pragma unroll 1
    for (int kc = 0; kc < 128; kc += 32) {
        __syncthreads();
        for (int idx = tid; idx < 32 * 128; idx += 256) {
            int k = idx >> 7, c = idx & 127;
            sB[idx] = W2[(kc + k) * 256 + cb + c];
        }
        for (int idx = tid; idx < 128 * 32; idx += 256) {
            int r = idx >> 5, k = idx & 31;
            int row = r0 + r;
            sA[r * 33 + k] = (row < NN) ? g_agg2[(long)row * 128 + kc + k] : 0.f;
        }
        __syncthreads();
#pragma unroll 8
        for (int k = 0; k < 32; k++) {
            float a[4];
#pragma unroll
            for (int i = 0; i < 4; i++) a[i] = sA[(ry * 4 + i) * 33 + k];
            const float4* B4 = (const float4*)(sB + k * 128);
#pragma unroll
            for (int q = 0; q < 4; q++) {
                float4 b = B4[cx * 4 + q];
#pragma unroll
                for (int i = 0; i < 4; i++) {
                    acc[i][q * 4 + 0] += a[i] * b.x;
                    acc[i][q * 4 + 1] += a[i] * b.y;
                    acc[i][q * 4 + 2] += a[i] * b.z;
                    acc[i][q * 4 + 3] += a[i] * b.w;
                }
            }
        }
    }
    int colb = cx * 16;
#pragma unroll
    for (int i = 0; i < 4; i++) {
        int row = r0 + ry * 4 + i;
        if (row < NN) {
            int g = batch[row];
            float* base = g_sums + g * 256 + cb + colb;
#pragma unroll
            for (int q = 0; q < 4; q++) {
                float vx = fmaxf(acc[i][q * 4 + 0] + b2[cb + colb + q * 4 + 0], 0.f);
                float vy = fmaxf(acc[i][q * 4 + 1] + b2[cb + colb + q * 4 + 1], 0.f);
                float vz = fmaxf(acc[i][q * 4 + 2] + b2[cb + colb + q * 4 + 2], 0.f);
                float vw = fmaxf(acc[i][q * 4 + 3] + b2[cb + colb + q * 4 + 3], 0.f);
                asm volatile("red.global.add.v4.f32 [%0], {%1,%2,%3,%4};"
                             :: "l"(base + q * 4), "f"(vx), "f"(vy), "f"(vz), "f"(vw)
                             : "memory");
            }
        }
    }
}

// ---------------- protein path -----------------------------------------------
__global__ void k_ptable(const float* __restrict__ emb,
                         const float* __restrict__ conv_w) {
    int idx = blockIdx.x * blockDim.x + threadIdx.x;
    if (idx < 25 * 8 * 64) {
        int o = idx & 63;
        int k = (idx >> 6) & 7;
        int tok = idx >> 9;
        float s = 0.f;
#pragma unroll 4
        for (int i = 0; i < 128; i++)
            s += emb[tok * 128 + i] * conv_w[o * 1024 + i * 8 + k];
        g_ptab[tok * 512 + k * 64 + o] = s;
    }
}

// conv1d(k=8) + relu + global max pool via the 25-token table.
__global__ __launch_bounds__(256) void k_conv(const int* __restrict__ seq,
                                              const float* __restrict__ conv_b) {
    __shared__ float2 stab[25 * 8 * 16];   // [tok][k][chan-pair]
    __shared__ int sseq[1024];
    __shared__ float2 sred[256];
    int tid = threadIdx.x;
    int b = blockIdx.x;
    int co = blockIdx.y * 32;

    for (int idx = tid; idx < 1024; idx += 256) sseq[idx] = seq[b * 1024 + idx];
    for (int idx = tid; idx < 25 * 8 * 16; idx += 256) {
        int p = idx & 15;
        int kk = (idx >> 4) & 7;
        int tok = idx >> 7;
        stab[idx] = make_float2(g_ptab[tok * 512 + kk * 64 + co + 2 * p],
                                g_ptab[tok * 512 + kk * 64 + co + 2 * p + 1]);
    }
    __syncthreads();

    int p = tid & 15;
    int phase = tid >> 4;
    float2 m = make_float2(-1e30f, -1e30f);
    for (int l = phase; l < 1017; l += 16) {
        float sx = 0.f, sy = 0.f;
#pragma unroll
        for (int k = 0; k < 8; k++) {
            float2 v = stab[(sseq[l + k] * 8 + k) * 16 + p];
            sx += v.x; sy += v.y;
        }
        m.x = fmaxf(m.x, sx);
        m.y = fmaxf(m.y, sy);
    }
    sred[tid] = m;
    __syncthreads();
    if (tid < 16) {
        float2 mm = sred[tid];
#pragma unroll
        for (int g = 1; g < 16; g++) {
            float2 v = sred[g * 16 + tid];
            mm.x = fmaxf(mm.x, v.x);
            mm.y = fmaxf(mm.y, v.y);
        }
        g_prot[b * 64 + co + 2 * tid]     = fmaxf(mm.x + conv_b[co + 2 * tid], 0.f);
        g_prot[b * 64 + co + 2 * tid + 1] = fmaxf(mm.y + conv_b[co + 2 * tid + 1], 0.f);
    }
}

__global__ void k_cnt(const int* __restrict__ batch) {
    int t = blockIdx.x * blockDim.x + threadIdx.x;
    if (t < NN) atomicAdd(&g_cnt[batch[t]], 1.0f);
}

// ---------------- final MLP ---------------------------------------------------
__global__ __launch_bounds__(256) void k_final(const float* __restrict__ fc1_w,
                                               const float* __restrict__ fc1_b,
                                               const float* __restrict__ fc2_w,
                                               const float* __restrict__ fc2_b,
                                               float* __restrict__ out) {
    __shared__ float comb[320];
    __shared__ float sred[256];
    int tid = threadIdx.x;
    int b = blockIdx.x;
    float invc = 1.0f / fmaxf(g_cnt[b], 1.0f);
    if (tid < 256) comb[tid] = g_sums[b * 256 + tid] * invc;
    if (tid < 64) comb[256 + tid] = g_prot[b * 64 + tid];
    __syncthreads();

    float part = 0.f;
#pragma unroll
    for (int rep = 0; rep < 2; rep++) {
        int o = tid + rep * 256;
        float acc = fc1_b[o];
#pragma unroll 4
        for (int j = 0; j < 320; j++)
            acc += comb[j] * fc1_w[j * 512 + o];
        part += fmaxf(acc, 0.f) * fc2_w[o];
    }
    sred[tid] = part;
    __syncthreads();
    for (int s = 128; s > 0; s >>= 1) {
        if (tid < s) sred[tid] += sred[tid + s];
        __syncthreads();
    }
    if (tid == 0) out[b] = sred[0] + fc2_b[0];
}

// ---------------- launch ------------------------------------------------------
extern "C" void kernel_launch(void* const* d_in, const int* in_sizes, int n_in,
                              void* d_out, int out_size) {
    const float* x       = (const float*)d_in[0];
    const int*   ei      = (const int*)  d_in[1];   // [2, NE]
    const int*   batch   = (const int*)  d_in[2];
    const int*   seq     = (const int*)  d_in[3];   // [NG, 1024]
    const float* W1      = (const float*)d_in[4];
    const float* b1      = (const float*)d_in[5];
    const float* W2      = (const float*)d_in[6];
    const float* b2      = (const float*)d_in[7];
    const float* emb     = (const float*)d_in[8];
    const float* conv_w  = (const float*)d_in[9];
    const float* conv_b  = (const float*)d_in[10];
    const float* fc1_w   = (const float*)d_in[11];
    const float* fc1_b   = (const float*)d_in[12];
    const float* fc2_w   = (const float*)d_in[13];
    const float* fc2_b   = (const float*)d_in[14];
    float* out = (float*)d_out;

    const int* src = ei;
    const int* dst = ei + NE;

    k_zero<<<512, 256>>>();                                   // 1
    k_deg<<<(NE + 255) / 256, 256>>>(dst);                    // 2
    k_init1<<<(NN * 20 + 255) / 256, 256>>>(x);               // 3
    k_scatter1<<<2048, 256>>>(x, src, dst);                   // 4  <- profiled
    k_gemm1<<<(NN + 127) / 128, 256>>>(W1, b1);               // 5
    k_init2<<<(NN * 32 + 255) / 256, 256>>>();                // 6
    k_scatter2<<<2048, 256>>>(src, dst);                      // 7
    {
        dim3 grid((NN + 127) / 128, 2);
        k_gemm2<<<grid, 256>>>(W2, b2, batch);                // 8
    }
    k_ptable<<<(25 * 8 * 64 + 255) / 256, 256>>>(emb, conv_w);// 9
    {
        dim3 grid(NG, 2);
        k_conv<<<grid, 256>>>(seq, conv_b);                   // 10
    }
    k_cnt<<<(NN + 255) / 256, 256>>>(batch);                  // 11
    k_final<<<NG, 256>>>(fc1_w, fc1_b, fc2_w, fc2_b, out);    // 12
}

// round 6
// speedup vs baseline: 1.1681x; 1.0074x over previous
#include <cuda_runtime.h>

#define NN 100000
#define NE 1600000
#define NG 512

// ---------------- scratch (device globals; no allocations allowed) ----------
__device__ int   g_cnti[NN];         // int in-degree counts (deg = cnti + 1)
__device__ float g_dinv[NN];         // rsqrt(deg)
__device__ float g_inv[NN];          // 1/deg
__device__ float g_x80[NN * 80];     // x padded to 80 cols (78,79 = 0)
__device__ float g_agg1[NN * 80];    // aggregated x (78 used, padded to 80)
__device__ float g_h1[NN * 128];     // relu(gcn1)
__device__ float g_agg2[NN * 128];   // aggregated h1
__device__ float g_sums[NG * 256];   // per-graph sums of h2
__device__ float g_cnt[NG];          // per-graph node counts
__device__ float g_ptab[25 * 8 * 64];// precomputed emb@conv_w table [tok][k][o]
__device__ float g_prot[NG * 64];    // protein features after maxpool

// ---------------- zero + degree count ----------------------------------------
__global__ void k_zero() {
    int t = blockIdx.x * blockDim.x + threadIdx.x;
    int stride = gridDim.x * blockDim.x;
    for (int i = t; i < NN; i += stride) g_cnti[i] = 0;
    for (int i = t; i < NG * 256; i += stride) g_sums[i] = 0.f;
    for (int i = t; i < NG; i += stride) g_cnt[i] = 0.f;
}

__global__ void k_deg(const int* __restrict__ dst) {
    int t = blockIdx.x * blockDim.x + threadIdx.x;
    if (t < NE) atomicAdd(&g_cnti[dst[t]], 1);
}

// init: g_x80 = x zero-padded to 80; agg1 = x80 / deg; dinv/inv per node.
// NN*20 threads: i = t/20, q = t%20 (one float4 each).
__global__ void k_init1(const float* __restrict__ x) {
    int t = blockIdx.x * blockDim.x + threadIdx.x;
    if (t < NN * 20) {
        int i = t / 20;
        int q = t - i * 20;
        float d = (float)g_cnti[i] + 1.0f;
        float inv = 1.0f / d;
        if (q == 0) {
            g_dinv[i] = rsqrtf(d);
            g_inv[i] = inv;
        }
        float4 raw;
        if (q < 19) {
            const float2* xp = (const float2*)(x + (long)i * 78 + q * 4);
            float2 a = xp[0], b = xp[1];
            raw = make_float4(a.x, a.y, b.x, b.y);
        } else {
            float2 a = *(const float2*)(x + (long)i * 78 + 76);
            raw = make_float4(a.x, a.y, 0.f, 0.f);
        }
        *(float4*)(g_x80 + (long)i * 80 + q * 4) = raw;
        *(float4*)(g_agg1 + (long)i * 80 + q * 4) =
            make_float4(raw.x * inv, raw.y * inv, raw.z * inv, raw.w * inv);
    }
}

// ---------------- edge scatter, layer 1 (flat chunk space, full lanes) -------
// chunk c <-> (edge e0 + c/20, quarter c%20); every lane active; unroll x2.
__global__ void k_scatter1(const int* __restrict__ src,
                           const int* __restrict__ dst) {
    const int W = 2048 * 8;                 // total warps
    const int EPW = (NE + W - 1) / W;       // 98 edges per warp
    int w = (blockIdx.x * blockDim.x + threadIdx.x) >> 5;
    int lane = threadIdx.x & 31;
    int e0 = w * EPW;
    if (e0 >= NE) return;
    int ecnt = min(EPW, NE - e0);
    int nchunk = ecnt * 20;

    int c = lane;
    for (; c + 32 < nchunk; c += 64) {
        int c0 = c, c1 = c + 32;
        int le0 = c0 / 20, q0 = c0 - le0 * 20;
        int le1 = c1 / 20, q1 = c1 - le1 * 20;
        int e0i = e0 + le0, e1i = e0 + le1;
        int s0 = __ldg(src + e0i), d0 = __ldg(dst + e0i);
        int s1 = __ldg(src + e1i), d1 = __ldg(dst + e1i);
        float n0 = __ldg(g_dinv + s0) * __ldg(g_dinv + d0);
        float n1 = __ldg(g_dinv + s1) * __ldg(g_dinv + d1);
        float4 v0 = *(const float4*)(g_x80 + (long)s0 * 80 + q0 * 4);
        float4 v1 = *(const float4*)(g_x80 + (long)s1 * 80 + q1 * 4);
        float* p0 = g_agg1 + (long)d0 * 80 + q0 * 4;
        float* p1 = g_agg1 + (long)d1 * 80 + q1 * 4;
        asm volatile("red.global.add.v4.f32 [%0], {%1,%2,%3,%4};"
                     :: "l"(p0), "f"(v0.x * n0), "f"(v0.y * n0),
                        "f"(v0.z * n0), "f"(v0.w * n0) : "memory");
        asm volatile("red.global.add.v4.f32 [%0], {%1,%2,%3,%4};"
                     :: "l"(p1), "f"(v1.x * n1), "f"(v1.y * n1),
                        "f"(v1.z * n1), "f"(v1.w * n1) : "memory");
    }
    for (; c < nchunk; c += 32) {
        int le = c / 20, q = c - le * 20;
        int e = e0 + le;
        int s = __ldg(src + e), d = __ldg(dst + e);
        float nrm = __ldg(g_dinv + s) * __ldg(g_dinv + d);
        float4 v = *(const float4*)(g_x80 + (long)s * 80 + q * 4);
        float* p = g_agg1 + (long)d * 80 + q * 4;
        asm volatile("red.global.add.v4.f32 [%0], {%1,%2,%3,%4};"
                     :: "l"(p), "f"(v.x * nrm), "f"(v.y * nrm),
                        "f"(v.z * nrm), "f"(v.w * nrm) : "memory");
    }
}

// ---------------- GEMM1: h1 = relu(agg1 @ W1 + b1); also agg2 = h1/deg ------
__global__ __launch_bounds__(256) void k_gemm1(const float* __restrict__ W1,
                                               const float* __restrict__ b1) {
    __shared__ float sA[128 * 41];
    __shared__ float sB[40 * 128];
    int tid = threadIdx.x;
    int r0 = blockIdx.x * 128;
    int cx = tid & 7, ry = tid >> 3;
    float acc[4][16];
#pragma unroll
    for (int i = 0; i < 4; i++)
#pragma unroll
        for (int j = 0; j < 16; j++) acc[i][j] = 0.f;

#pragma unroll 1
    for (int kc = 0; kc < 80; kc += 40) {
        __syncthreads();
        for (int idx = tid; idx < 40 * 128; idx += 256) {
            int k = idx >> 7, c = idx & 127;
            int gk = kc + k;
            sB[idx] = (gk < 78) ? W1[gk * 128 + c] : 0.f;
        }
        for (int idx = tid; idx < 128 * 40; idx += 256) {
            int r = idx / 40, k = idx - r * 40;
            int row = r0 + r;
            sA[r * 41 + k] = (row < NN) ? g_agg1[(long)row * 80 + kc + k] : 0.f;
        }
        __syncthreads();
#pragma unroll 8
        for (int k = 0; k < 40; k++) {
            float a[4];
#pragma unroll
            for (int i = 0; i < 4; i++) a[i] = sA[(ry * 4 + i) * 41 + k];
            const float4* B4 = (const float4*)(sB + k * 128);
#pragma unroll
            for (int q = 0; q < 4; q++) {
                float4 b = B4[cx * 4 + q];
#pragma unroll
                for (int i = 0; i < 4; i++) {
                    acc[i][q * 4 + 0] += a[i] * b.x;
                    acc[i][q * 4 + 1] += a[i] * b.y;
                    acc[i][q * 4 + 2] += a[i] * b.z;
                    acc[i][q * 4 + 3] += a[i] * b.w;
                }
            }
        }
    }
    int colb = cx * 16;
#pragma unroll
    for (int i = 0; i < 4; i++) {
        int row = r0 + ry * 4 + i;
        if (row < NN) {
            float inv = __ldg(g_inv + row);
#pragma unroll
            for (int q = 0; q < 4; q++) {
                float4 v;
                v.x = fmaxf(acc[i][q * 4 + 0] + b1[colb + q * 4 + 0], 0.f);
                v.y = fmaxf(acc[i][q * 4 + 1] + b1[colb + q * 4 + 1], 0.f);
                v.z = fmaxf(acc[i][q * 4 + 2] + b1[colb + q * 4 + 2], 0.f);
                v.w = fmaxf(acc[i][q * 4 + 3] + b1[colb + q * 4 + 3], 0.f);
                *(float4*)(g_h1 + (long)row * 128 + colb + q * 4) = v;
                *(float4*)(g_agg2 + (long)row * 128 + colb + q * 4) =
                    make_float4(v.x * inv, v.y * inv, v.z * inv, v.w * inv);
            }
        }
    }
}

// ---------------- edge scatter, layer 2 (128 floats / edge, unroll x4) ------
__global__ void k_scatter2(const int* __restrict__ src,
                           const int* __restrict__ dst) {
    const int W = 2048 * 8;
    const int EPW = (NE + W - 1) / W;
    int w = (blockIdx.x * blockDim.x + threadIdx.x) >> 5;
    int lane = threadIdx.x & 31;
    int e = w * EPW;
    int end = min(e + EPW, NE);
    if (e >= NE) return;

    for (; e + 3 < end; e += 4) {
        int s0 = __ldg(src + e),     d0 = __ldg(dst + e);
        int s1 = __ldg(src + e + 1), d1 = __ldg(dst + e + 1);
        int s2 = __ldg(src + e + 2), d2 = __ldg(dst + e + 2);
        int s3 = __ldg(src + e + 3), d3 = __ldg(dst + e + 3);
        float n0 = __ldg(g_dinv + s0) * __ldg(g_dinv + d0);
        float n1 = __ldg(g_dinv + s1) * __ldg(g_dinv + d1);
        float n2 = __ldg(g_dinv + s2) * __ldg(g_dinv + d2);
        float n3 = __ldg(g_dinv + s3) * __ldg(g_dinv + d3);
        float4 v0 = ((const float4*)(g_h1 + (long)s0 * 128))[lane];
        float4 v1 = ((const float4*)(g_h1 + (long)s1 * 128))[lane];
        float4 v2 = ((const float4*)(g_h1 + (long)s2 * 128))[lane];
        float4 v3 = ((const float4*)(g_h1 + (long)s3 * 128))[lane];
        float* p0 = g_agg2 + (long)d0 * 128 + lane * 4;
        float* p1 = g_agg2 + (long)d1 * 128 + lane * 4;
        float* p2 = g_agg2 + (long)d2 * 128 + lane * 4;
        float* p3 = g_agg2 + (long)d3 * 128 + lane * 4;
        asm volatile("red.global.add.v4.f32 [%0], {%1,%2,%3,%4};"
                     :: "l"(p0), "f"(v0.x * n0), "f"(v0.y * n0),
                        "f"(v0.z * n0), "f"(v0.w * n0) : "memory");
        asm volatile("red.global.add.v4.f32 [%0], {%1,%2,%3,%4};"
                     :: "l"(p1), "f"(v1.x * n1), "f"(v1.y * n1),
                        "f"(v1.z * n1), "f"(v1.w * n1) : "memory");
        asm volatile("red.global.add.v4.f32 [%0], {%1,%2,%3,%4};"
                     :: "l"(p2), "f"(v2.x * n2), "f"(v2.y * n2),
                        "f"(v2.z * n2), "f"(v2.w * n2) : "memory");
        asm volatile("red.global.add.v4.f32 [%0], {%1,%2,%3,%4};"
                     :: "l"(p3), "f"(v3.x * n3), "f"(v3.y * n3),
                        "f"(v3.z * n3), "f"(v3.w * n3) : "memory");
    }
    for (; e < end; e++) {
        int s = __ldg(src + e), d = __ldg(dst + e);
        float nrm = __ldg(g_dinv + s) * __ldg(g_dinv + d);
        float4 v = ((const float4*)(g_h1 + (long)s * 128))[lane];
        float* p = g_agg2 + (long)d * 128 + lane * 4;
        asm volatile("red.global.add.v4.f32 [%0], {%1,%2,%3,%4};"
                     :: "l"(p), "f"(v.x * nrm), "f"(v.y * nrm),
                        "f"(v.z * nrm), "f"(v.w * nrm) : "memory");
    }
}

// ---------------- GEMM2 + fused mean-pool epilogue ---------------------------
__global__ __launch_bounds__(256) void k_gemm2(const float* __restrict__ W2,
                                               const float* __restrict__ b2,
                                               const int* __restrict__ batch) {
    __shared__ float sA[128 * 33];
    __shared__ float sB[32 * 128];
    int tid = threadIdx.x;
    int r0 = blockIdx.x * 128;
    int cb = blockIdx.y * 128;
    int cx = tid & 7, ry = tid >> 3;
    float acc[4][16];
#pragma unroll
    for (int i = 0; i < 4; i++)
#pragma unroll
        for (int j = 0; j < 16; j++) acc[i][j] = 0.f;

#pragma unroll 1
    for (int kc = 0; kc < 128; kc += 32) {
        __syncthreads();
        for (int idx = tid; idx < 32 * 128; idx += 256) {
            int k = idx >> 7, c = idx & 127;
            sB[idx] = W2[(kc + k) * 256 + cb + c];
        }
        for (int idx = tid; idx < 128 * 32; idx += 256) {
            int r = idx >> 5, k = idx & 31;
            int row = r0 + r;
            sA[r * 33 + k] = (row < NN) ? g_agg2[(long)row * 128 + kc + k] : 0.f;
        }
        __syncthreads();
#pragma unroll 8
        for (int k = 0; k < 32; k++) {
            float a[4];
#pragma unroll
            for (int i = 0; i < 4; i++) a[i] = sA[(ry * 4 + i) * 33 + k];
            const float4* B4 = (const float4*)(sB + k * 128);
#pragma unroll
            for (int q = 0; q < 4; q++) {
                float4 b = B4[cx * 4 + q];
#pragma unroll
                for (int i = 0; i < 4; i++) {
                    acc[i][q * 4 + 0] += a[i] * b.x;
                    acc[i][q * 4 + 1] += a[i] * b.y;
                    acc[i][q * 4 + 2] += a[i] * b.z;
                    acc[i][q * 4 + 3] += a[i] * b.w;
                }
            }
        }
    }
    int colb = cx * 16;
#pragma unroll
    for (int i = 0; i < 4; i++) {
        int row = r0 + ry * 4 + i;
        if (row < NN) {
            int g = batch[row];
            float* base = g_sums + g * 256 + cb + colb;
#pragma unroll
            for (int q = 0; q < 4; q++) {
                float vx = fmaxf(acc[i][q * 4 + 0] + b2[cb + colb + q * 4 + 0], 0.f);
                float vy = fmaxf(acc[i][q * 4 + 1] + b2[cb + colb + q * 4 + 1], 0.f);
                float vz = fmaxf(acc[i][q * 4 + 2] + b2[cb + colb + q * 4 + 2], 0.f);
                float vw = fmaxf(acc[i][q * 4 + 3] + b2[cb + colb + q * 4 + 3], 0.f);
                asm volatile("red.global.add.v4.f32 [%0], {%1,%2,%3,%4};"
                             :: "l"(base + q * 4), "f"(vx), "f"(vy), "f"(vz), "f"(vw)
                             : "memory");
            }
        }
    }
}

// ---------------- protein path -----------------------------------------------
__global__ void k_ptable(const float* __restrict__ emb,
                         const float* __restrict__ conv_w) {
    int idx = blockIdx.x * blockDim.x + threadIdx.x;
    if (idx < 25 * 8 * 64) {
        int o = idx & 63;
        int k = (idx >> 6) & 7;
        int tok = idx >> 9;
        float s = 0.f;
#pragma unroll 4
        for (int i = 0; i < 128; i++)
            s += emb[tok * 128 + i] * conv_w[o * 1024 + i * 8 + k];
        g_ptab[tok * 512 + k * 64 + o] = s;
    }
}

__global__ __launch_bounds__(256) void k_conv(const int* __restrict__ seq,
                                              const float* __restrict__ conv_b) {
    __shared__ float2 stab[25 * 8 * 16];   // [tok][k][chan-pair]
    __shared__ int sseq[1024];
    __shared__ float2 sred[256];
    int tid = threadIdx.x;
    int b = blockIdx.x;
    int co = blockIdx.y * 32;

    for (int idx = tid; idx < 1024; idx += 256) sseq[idx] = seq[b * 1024 + idx];
    for (int idx = tid; idx < 25 * 8 * 16; idx += 256) {
        int p = idx & 15;
        int kk = (idx >> 4) & 7;
        int tok = idx >> 7;
        stab[idx] = make_float2(g_ptab[tok * 512 + kk * 64 + co + 2 * p],
                                g_ptab[tok * 512 + kk * 64 + co + 2 * p + 1]);
    }
    __syncthreads();

    int p = tid & 15;
    int phase = tid >> 4;
    float2 m = make_float2(-1e30f, -1e30f);
    for (int l = phase; l < 1017; l += 16) {
        float sx = 0.f, sy = 0.f;
#pragma unroll
        for (int k = 0; k < 8; k++) {
            float2 v = stab[(sseq[l + k] * 8 + k) * 16 + p];
            sx += v.x; sy += v.y;
        }
        m.x = fmaxf(m.x, sx);
        m.y = fmaxf(m.y, sy);
    }
    sred[tid] = m;
    __syncthreads();
    if (tid < 16) {
        float2 mm = sred[tid];
#pragma unroll
        for (int g = 1; g < 16; g++) {
            float2 v = sred[g * 16 + tid];
            mm.x = fmaxf(mm.x, v.x);
            mm.y = fmaxf(mm.y, v.y);
        }
        g_prot[b * 64 + co + 2 * tid]     = fmaxf(mm.x + conv_b[co + 2 * tid], 0.f);
        g_prot[b * 64 + co + 2 * tid + 1] = fmaxf(mm.y + conv_b[co + 2 * tid + 1], 0.f);
    }
}

__global__ void k_cnt(const int* __restrict__ batch) {
    int t = blockIdx.x * blockDim.x + threadIdx.x;
    if (t < NN) atomicAdd(&g_cnt[batch[t]], 1.0f);
}

// ---------------- final MLP ---------------------------------------------------
__global__ __launch_bounds__(256) void k_final(const float* __restrict__ fc1_w,
                                               const float* __restrict__ fc1_b,
                                               const float* __restrict__ fc2_w,
                                               const float* __restrict__ fc2_b,
                                               float* __restrict__ out) {
    __shared__ float comb[320];
    __shared__ float sred[256];
    int tid = threadIdx.x;
    int b = blockIdx.x;
    float invc = 1.0f / fmaxf(g_cnt[b], 1.0f);
    if (tid < 256) comb[tid] = g_sums[b * 256 + tid] * invc;
    if (tid < 64) comb[256 + tid] = g_prot[b * 64 + tid];
    __syncthreads();

    float part = 0.f;
#pragma unroll
    for (int rep = 0; rep < 2; rep++) {
        int o = tid + rep * 256;
        float acc = fc1_b[o];
#pragma unroll 4
        for (int j = 0; j < 320; j++)
            acc += comb[j] * fc1_w[j * 512 + o];
        part += fmaxf(acc, 0.f) * fc2_w[o];
    }
    sred[tid] = part;
    __syncthreads();
    for (int s = 128; s > 0; s >>= 1) {
        if (tid < s) sred[tid] += sred[tid + s];
        __syncthreads();
    }
    if (tid == 0) out[b] = sred[0] + fc2_b[0];
}

// ---------------- launch ------------------------------------------------------
extern "C" void kernel_launch(void* const* d_in, const int* in_sizes, int n_in,
                              void* d_out, int out_size) {
    const float* x       = (const float*)d_in[0];
    const int*   ei      = (const int*)  d_in[1];   // [2, NE]
    const int*   batch   = (const int*)  d_in[2];
    const int*   seq     = (const int*)  d_in[3];   // [NG, 1024]
    const float* W1      = (const float*)d_in[4];
    const float* b1      = (const float*)d_in[5];
    const float* W2      = (const float*)d_in[6];
    const float* b2      = (const float*)d_in[7];
    const float* emb     = (const float*)d_in[8];
    const float* conv_w  = (const float*)d_in[9];
    const float* conv_b  = (const float*)d_in[10];
    const float* fc1_w   = (const float*)d_in[11];
    const float* fc1_b   = (const float*)d_in[12];
    const float* fc2_w   = (const float*)d_in[13];
    const float* fc2_b   = (const float*)d_in[14];
    float* out = (float*)d_out;

    const int* src = ei;
    const int* dst = ei + NE;

    k_zero<<<512, 256>>>();                                   // 1
    k_deg<<<(NE + 255) / 256, 256>>>(dst);                    // 2
    k_init1<<<(NN * 20 + 255) / 256, 256>>>(x);               // 3
    k_scatter1<<<2048, 256>>>(src, dst);                      // 4  <- profiled
    k_gemm1<<<(NN + 127) / 128, 256>>>(W1, b1);               // 5
    k_scatter2<<<2048, 256>>>(src, dst);                      // 6
    {
        dim3 grid((NN + 127) / 128, 2);
        k_gemm2<<<grid, 256>>>(W2, b2, batch);                // 7
    }
    k_ptable<<<(25 * 8 * 64 + 255) / 256, 256>>>(emb, conv_w);// 8
    {
        dim3 grid(NG, 2);
        k_conv<<<grid, 256>>>(seq, conv_b);                   // 9
    }
    k_cnt<<<(NN + 255) / 256, 256>>>(batch);                  // 10
    k_final<<<NG, 256>>>(fc1_w, fc1_b, fc2_w, fc2_b, out);    // 11
}

// round 7
// speedup vs baseline: 1.2927x; 1.1066x over previous
#include <cuda_runtime.h>
#include <cuda_fp16.h>

#define NN 100000
#define NE 1600000
#define NG 512

// ---------------- scratch (device globals; no allocations allowed) ----------
__device__ int   g_cnti[NN];         // int in-degree counts (deg = cnti + 1)
__device__ float g_dinv[NN];         // rsqrt(deg)
__device__ float g_inv[NN];          // 1/deg
__device__ float g_x80[NN * 80];     // x padded to 80 cols (78,79 = 0)
__device__ float g_agg1[NN * 80];    // aggregated x (78 used, padded to 80)
__device__ uint4 g_h1v[NN * 16];     // relu(gcn1) as __half[NN*128]
__device__ uint4 g_agg2v[NN * 16];   // aggregated h1 as __half[NN*128]
__device__ float g_sums[NG * 256];   // per-graph sums of h2
__device__ float g_cnt[NG];          // per-graph node counts
__device__ float g_ptab[25 * 8 * 64];// precomputed emb@conv_w table [tok][k][o]
__device__ float g_prot[NG * 64];    // protein features after maxpool

// ---------------- zero + degree count ----------------------------------------
__global__ void k_zero() {
    int t = blockIdx.x * blockDim.x + threadIdx.x;
    int stride = gridDim.x * blockDim.x;
    for (int i = t; i < NN; i += stride) g_cnti[i] = 0;
    for (int i = t; i < NG * 256; i += stride) g_sums[i] = 0.f;
    for (int i = t; i < NG; i += stride) g_cnt[i] = 0.f;
}

__global__ void k_deg(const int* __restrict__ dst) {
    int t = blockIdx.x * blockDim.x + threadIdx.x;
    if (t < NE) atomicAdd(&g_cnti[dst[t]], 1);
}

// init: g_x80 = x zero-padded to 80; agg1 = x80 / deg; dinv/inv per node.
__global__ void k_init1(const float* __restrict__ x) {
    int t = blockIdx.x * blockDim.x + threadIdx.x;
    if (t < NN * 20) {
        int i = t / 20;
        int q = t - i * 20;
        float d = (float)g_cnti[i] + 1.0f;
        float inv = 1.0f / d;
        if (q == 0) {
            g_dinv[i] = rsqrtf(d);
            g_inv[i] = inv;
        }
        float4 raw;
        if (q < 19) {
            const float2* xp = (const float2*)(x + (long)i * 78 + q * 4);
            float2 a = xp[0], b = xp[1];
            raw = make_float4(a.x, a.y, b.x, b.y);
        } else {
            float2 a = *(const float2*)(x + (long)i * 78 + 76);
            raw = make_float4(a.x, a.y, 0.f, 0.f);
        }
        *(float4*)(g_x80 + (long)i * 80 + q * 4) = raw;
        *(float4*)(g_agg1 + (long)i * 80 + q * 4) =
            make_float4(raw.x * inv, raw.y * inv, raw.z * inv, raw.w * inv);
    }
}

// ---------------- edge scatter, layer 1 (flat chunk space, full lanes) -------
__global__ void k_scatter1(const int* __restrict__ src,
                           const int* __restrict__ dst) {
    const int W = 2048 * 8;                 // total warps
    const int EPW = (NE + W - 1) / W;       // 98 edges per warp
    int w = (blockIdx.x * blockDim.x + threadIdx.x) >> 5;
    int lane = threadIdx.x & 31;
    int e0 = w * EPW;
    if (e0 >= NE) return;
    int ecnt = min(EPW, NE - e0);
    int nchunk = ecnt * 20;

    int c = lane;
    for (; c + 32 < nchunk; c += 64) {
        int c0 = c, c1 = c + 32;
        int le0 = c0 / 20, q0 = c0 - le0 * 20;
        int le1 = c1 / 20, q1 = c1 - le1 * 20;
        int e0i = e0 + le0, e1i = e0 + le1;
        int s0 = __ldg(src + e0i), d0 = __ldg(dst + e0i);
        int s1 = __ldg(src + e1i), d1 = __ldg(dst + e1i);
        float n0 = __ldg(g_dinv + s0) * __ldg(g_dinv + d0);
        float n1 = __ldg(g_dinv + s1) * __ldg(g_dinv + d1);
        float4 v0 = *(const float4*)(g_x80 + (long)s0 * 80 + q0 * 4);
        float4 v1 = *(const float4*)(g_x80 + (long)s1 * 80 + q1 * 4);
        float* p0 = g_agg1 + (long)d0 * 80 + q0 * 4;
        float* p1 = g_agg1 + (long)d1 * 80 + q1 * 4;
        asm volatile("red.global.add.v4.f32 [%0], {%1,%2,%3,%4};"
                     :: "l"(p0), "f"(v0.x * n0), "f"(v0.y * n0),
                        "f"(v0.z * n0), "f"(v0.w * n0) : "memory");
        asm volatile("red.global.add.v4.f32 [%0], {%1,%2,%3,%4};"
                     :: "l"(p1), "f"(v1.x * n1), "f"(v1.y * n1),
                        "f"(v1.z * n1), "f"(v1.w * n1) : "memory");
    }
    for (; c < nchunk; c += 32) {
        int le = c / 20, q = c - le * 20;
        int e = e0 + le;
        int s = __ldg(src + e), d = __ldg(dst + e);
        float nrm = __ldg(g_dinv + s) * __ldg(g_dinv + d);
        float4 v = *(const float4*)(g_x80 + (long)s * 80 + q * 4);
        float* p = g_agg1 + (long)d * 80 + q * 4;
        asm volatile("red.global.add.v4.f32 [%0], {%1,%2,%3,%4};"
                     :: "l"(p), "f"(v.x * nrm), "f"(v.y * nrm),
                        "f"(v.z * nrm), "f"(v.w * nrm) : "memory");
    }
}

// ---------------- GEMM1: h1 = relu(agg1 @ W1 + b1) (f16); agg2 = h1/deg (f16)
__global__ __launch_bounds__(256) void k_gemm1(const float* __restrict__ W1,
                                               const float* __restrict__ b1) {
    __shared__ float sA[128 * 41];
    __shared__ float sB[40 * 128];
    int tid = threadIdx.x;
    int r0 = blockIdx.x * 128;
    int cx = tid & 7, ry = tid >> 3;
    float acc[4][16];
#pragma unroll
    for (int i = 0; i < 4; i++)
#pragma unroll
        for (int j = 0; j < 16; j++) acc[i][j] = 0.f;

#pragma unroll 1
    for (int kc = 0; kc < 80; kc += 40) {
        __syncthreads();
        for (int idx = tid; idx < 40 * 128; idx += 256) {
            int k = idx >> 7, c = idx & 127;
            int gk = kc + k;
            sB[idx] = (gk < 78) ? W1[gk * 128 + c] : 0.f;
        }
        for (int idx = tid; idx < 128 * 40; idx += 256) {
            int r = idx / 40, k = idx - r * 40;
            int row = r0 + r;
            sA[r * 41 + k] = (row < NN) ? g_agg1[(long)row * 80 + kc + k] : 0.f;
        }
        __syncthreads();
#pragma unroll 8
        for (int k = 0; k < 40; k++) {
            float a[4];
#pragma unroll
            for (int i = 0; i < 4; i++) a[i] = sA[(ry * 4 + i) * 41 + k];
            const float4* B4 = (const float4*)(sB + k * 128);
#pragma unroll
            for (int q = 0; q < 4; q++) {
                float4 b = B4[cx * 4 + q];
#pragma unroll
                for (int i = 0; i < 4; i++) {
                    acc[i][q * 4 + 0] += a[i] * b.x;
                    acc[i][q * 4 + 1] += a[i] * b.y;
                    acc[i][q * 4 + 2] += a[i] * b.z;
                    acc[i][q * 4 + 3] += a[i] * b.w;
                }
            }
        }
    }
    int colb = cx * 16;
    __half* h1 = (__half*)g_h1v;
    __half* a2 = (__half*)g_agg2v;
#pragma unroll
    for (int i = 0; i < 4; i++) {
        int row = r0 + ry * 4 + i;
        if (row < NN) {
            float inv = __ldg(g_inv + row);
#pragma unroll
            for (int q = 0; q < 4; q++) {
                float vx = fmaxf(acc[i][q * 4 + 0] + b1[colb + q * 4 + 0], 0.f);
                float vy = fmaxf(acc[i][q * 4 + 1] + b1[colb + q * 4 + 1], 0.f);
                float vz = fmaxf(acc[i][q * 4 + 2] + b1[colb + q * 4 + 2], 0.f);
                float vw = fmaxf(acc[i][q * 4 + 3] + b1[colb + q * 4 + 3], 0.f);
                __half2 h0 = __floats2half2_rn(vx, vy);
                __half2 h1p = __floats2half2_rn(vz, vw);
                *(__half2*)(h1 + (long)row * 128 + colb + q * 4)     = h0;
                *(__half2*)(h1 + (long)row * 128 + colb + q * 4 + 2) = h1p;
                __half2 a0 = __floats2half2_rn(vx * inv, vy * inv);
                __half2 a1 = __floats2half2_rn(vz * inv, vw * inv);
                *(__half2*)(a2 + (long)row * 128 + colb + q * 4)     = a0;
                *(__half2*)(a2 + (long)row * 128 + colb + q * 4 + 2) = a1;
            }
        }
    }
}

// ---------------- edge scatter, layer 2 (f16, half-warp per edge) -----------
// 128 halves = 256 B per row = 16 x uint4; lanes 0-15 edge e, 16-31 edge e+1.
__device__ __forceinline__ void red_f16x8(__half* p, uint4 v, __half2 nh) {
    __half2 h0 = __hmul2(*(const __half2*)&v.x, nh);
    __half2 h1 = __hmul2(*(const __half2*)&v.y, nh);
    __half2 h2 = __hmul2(*(const __half2*)&v.z, nh);
    __half2 h3 = __hmul2(*(const __half2*)&v.w, nh);
    asm volatile("red.global.add.noftz.v4.f16x2 [%0], {%1,%2,%3,%4};"
                 :: "l"(p),
                    "r"(*(const unsigned int*)&h0), "r"(*(const unsigned int*)&h1),
                    "r"(*(const unsigned int*)&h2), "r"(*(const unsigned int*)&h3)
                 : "memory");
}

__global__ void k_scatter2(const int* __restrict__ src,
                           const int* __restrict__ dst) {
    const int W = 2048 * 8;
    const int EPW = (NE + W - 1) / W;       // 98
    int w = (blockIdx.x * blockDim.x + threadIdx.x) >> 5;
    int lane = threadIdx.x & 31;
    int half = lane >> 4;                   // 0 or 1: which edge of the pair
    int q = lane & 15;                      // uint4 index within the row
    int e = w * EPW;
    int end = min(e + EPW, NE);
    if (e >= NE) return;
    const __half* h1 = (const __half*)g_h1v;
    __half* agg = (__half*)g_agg2v;

    for (; e + 3 < end; e += 4) {
        int ea = e + half, eb = e + 2 + half;
        int sa = __ldg(src + ea), da = __ldg(dst + ea);
        int sb = __ldg(src + eb), db = __ldg(dst + eb);
        float na = __ldg(g_dinv + sa) * __ldg(g_dinv + da);
        float nb = __ldg(g_dinv + sb) * __ldg(g_dinv + db);
        uint4 va = ((const uint4*)(h1 + (long)sa * 128))[q];
        uint4 vb = ((const uint4*)(h1 + (long)sb * 128))[q];
        red_f16x8(agg + (long)da * 128 + q * 8, va, __float2half2_rn(na));
        red_f16x8(agg + (long)db * 128 + q * 8, vb, __float2half2_rn(nb));
    }
    for (; e < end; e += 2) {
        if (e + half < end) {
            int ei = e + half;
            int s = __ldg(src + ei), d = __ldg(dst + ei);
            float nrm = __ldg(g_dinv + s) * __ldg(g_dinv + d);
            uint4 v = ((const uint4*)(h1 + (long)s * 128))[q];
            red_f16x8(agg + (long)d * 128 + q * 8, v, __float2half2_rn(nrm));
        }
    }
}

// ---------------- GEMM2 + fused mean-pool epilogue ---------------------------
__global__ __launch_bounds__(256) void k_gemm2(const float* __restrict__ W2,
                                               const float* __restrict__ b2,
                                               const int* __restrict__ batch) {
    __shared__ float sA[128 * 33];
    __shared__ float sB[32 * 128];
    int tid = threadIdx.x;
    int r0 = blockIdx.x * 128;
    int cb = blockIdx.y * 128;
    int cx = tid & 7, ry = tid >> 3;
    const __half* a2 = (const __half*)g_agg2v;
    float acc[4][16];
#pragma unroll
    for (int i = 0; i < 4; i++)
#pragma unroll
        for (int j = 0; j < 16; j++) acc[i][j] = 0.f;

#pragma unroll 1
    for (int kc = 0; kc < 128; kc += 32) {
        __syncthreads();
        for (int idx = tid; idx < 32 * 128; idx += 256) {
            int k = idx >> 7, c = idx & 127;
            sB[idx] = W2[(kc + k) * 256 + cb + c];
        }
        for (int idx = tid; idx < 128 * 32; idx += 256) {
            int r = idx >> 5, k = idx & 31;
            int row = r0 + r;
            sA[r * 33 + k] = (row < NN)
                ? __half2float(a2[(long)row * 128 + kc + k]) : 0.f;
        }
        __syncthreads();
#pragma unroll 8
        for (int k = 0; k < 32; k++) {
            float a[4];
#pragma unroll
            for (int i = 0; i < 4; i++) a[i] = sA[(ry * 4 + i) * 33 + k];
            const float4* B4 = (const float4*)(sB + k * 128);
#pragma unroll
            for (int q = 0; q < 4; q++) {
                float4 b = B4[cx * 4 + q];
#pragma unroll
                for (int i = 0; i < 4; i++) {
                    acc[i][q * 4 + 0] += a[i] * b.x;
                    acc[i][q * 4 + 1] += a[i] * b.y;
                    acc[i][q * 4 + 2] += a[i] * b.z;
                    acc[i][q * 4 + 3] += a[i] * b.w;
                }
            }
        }
    }
    int colb = cx * 16;
#pragma unroll
    for (int i = 0; i < 4; i++) {
        int row = r0 + ry * 4 + i;
        if (row < NN) {
            int g = batch[row];
            float* base = g_sums + g * 256 + cb + colb;
#pragma unroll
            for (int q = 0; q < 4; q++) {
                float vx = fmaxf(acc[i][q * 4 + 0] + b2[cb + colb + q * 4 + 0], 0.f);
                float vy = fmaxf(acc[i][q * 4 + 1] + b2[cb + colb + q * 4 + 1], 0.f);
                float vz = fmaxf(acc[i][q * 4 + 2] + b2[cb + colb + q * 4 + 2], 0.f);
                float vw = fmaxf(acc[i][q * 4 + 3] + b2[cb + colb + q * 4 + 3], 0.f);
                asm volatile("red.global.add.v4.f32 [%0], {%1,%2,%3,%4};"
                             :: "l"(base + q * 4), "f"(vx), "f"(vy), "f"(vz), "f"(vw)
                             : "memory");
            }
        }
    }
}

// ---------------- protein path -----------------------------------------------
__global__ void k_ptable(const float* __restrict__ emb,
                         const float* __restrict__ conv_w) {
    int idx = blockIdx.x * blockDim.x + threadIdx.x;
    if (idx < 25 * 8 * 64) {
        int o = idx & 63;
        int k = (idx >> 6) & 7;
        int tok = idx >> 9;
        float s = 0.f;
#pragma unroll 4
        for (int i = 0; i < 128; i++)
            s += emb[tok * 128 + i] * conv_w[o * 1024 + i * 8 + k];
        g_ptab[tok * 512 + k * 64 + o] = s;
    }
}

__global__ __launch_bounds__(256) void k_conv(const int* __restrict__ seq,
                                              const float* __restrict__ conv_b) {
    __shared__ float2 stab[25 * 8 * 16];   // [tok][k][chan-pair]
    __shared__ int sseq[1024];
    __shared__ float2 sred[256];
    int tid = threadIdx.x;
    int b = blockIdx.x;
    int co = blockIdx.y * 32;

    for (int idx = tid; idx < 1024; idx += 256) sseq[idx] = seq[b * 1024 + idx];
    for (int idx = tid; idx < 25 * 8 * 16; idx += 256) {
        int p = idx & 15;
        int kk = (idx >> 4) & 7;
        int tok = idx >> 7;
        stab[idx] = make_float2(g_ptab[tok * 512 + kk * 64 + co + 2 * p],
                                g_ptab[tok * 512 + kk * 64 + co + 2 * p + 1]);
    }
    __syncthreads();

    int p = tid & 15;
    int phase = tid >> 4;
    float2 m = make_float2(-1e30f, -1e30f);
    for (int l = phase; l < 1017; l += 16) {
        float sx = 0.f, sy = 0.f;
#pragma unroll
        for (int k = 0; k < 8; k++) {
            float2 v = stab[(sseq[l + k] * 8 + k) * 16 + p];
            sx += v.x; sy += v.y;
        }
        m.x = fmaxf(m.x, sx);
        m.y = fmaxf(m.y, sy);
    }
    sred[tid] = m;
    __syncthreads();
    if (tid < 16) {
        float2 mm = sred[tid];
#pragma unroll
        for (int g = 1; g < 16; g++) {
            float2 v = sred[g * 16 + tid];
            mm.x = fmaxf(mm.x, v.x);
            mm.y = fmaxf(mm.y, v.y);
        }
        g_prot[b * 64 + co + 2 * tid]     = fmaxf(mm.x + conv_b[co + 2 * tid], 0.f);
        g_prot[b * 64 + co + 2 * tid + 1] = fmaxf(mm.y + conv_b[co + 2 * tid + 1], 0.f);
    }
}

__global__ void k_cnt(const int* __restrict__ batch) {
    int t = blockIdx.x * blockDim.x + threadIdx.x;
    if (t < NN) atomicAdd(&g_cnt[batch[t]], 1.0f);
}

// ---------------- final MLP ---------------------------------------------------
__global__ __launch_bounds__(256) void k_final(const float* __restrict__ fc1_w,
                                               const float* __restrict__ fc1_b,
                                               const float* __restrict__ fc2_w,
                                               const float* __restrict__ fc2_b,
                                               float* __restrict__ out) {
    __shared__ float comb[320];
    __shared__ float sred[256];
    int tid = threadIdx.x;
    int b = blockIdx.x;
    float invc = 1.0f / fmaxf(g_cnt[b], 1.0f);
    if (tid < 256) comb[tid] = g_sums[b * 256 + tid] * invc;
    if (tid < 64) comb[256 + tid] = g_prot[b * 64 + tid];
    __syncthreads();

    float part = 0.f;
#pragma unroll
    for (int rep = 0; rep < 2; rep++) {
        int o = tid + rep * 256;
        float acc = fc1_b[o];
#pragma unroll 4
        for (int j = 0; j < 320; j++)
            acc += comb[j] * fc1_w[j * 512 + o];
        part += fmaxf(acc, 0.f) * fc2_w[o];
    }
    sred[tid] = part;
    __syncthreads();
    for (int s = 128; s > 0; s >>= 1) {
        if (tid < s) sred[tid] += sred[tid + s];
        __syncthreads();
    }
    if (tid == 0) out[b] = sred[0] + fc2_b[0];
}

// ---------------- launch ------------------------------------------------------
extern "C" void kernel_launch(void* const* d_in, const int* in_sizes, int n_in,
                              void* d_out, int out_size) {
    const float* x       = (const float*)d_in[0];
    const int*   ei      = (const int*)  d_in[1];   // [2, NE]
    const int*   batch   = (const int*)  d_in[2];
    const int*   seq     = (const int*)  d_in[3];   // [NG, 1024]
    const float* W1      = (const float*)d_in[4];
    const float* b1      = (const float*)d_in[5];
    const float* W2      = (const float*)d_in[6];
    const float* b2      = (const float*)d_in[7];
    const float* emb     = (const float*)d_in[8];
    const float* conv_w  = (const float*)d_in[9];
    const float* conv_b  = (const float*)d_in[10];
    const float* fc1_w   = (const float*)d_in[11];
    const float* fc1_b   = (const float*)d_in[12];
    const float* fc2_w   = (const float*)d_in[13];
    const float* fc2_b   = (const float*)d_in[14];
    float* out = (float*)d_out;

    const int* src = ei;
    const int* dst = ei + NE;

    k_zero<<<512, 256>>>();                                   // 1
    k_deg<<<(NE + 255) / 256, 256>>>(dst);                    // 2
    k_init1<<<(NN * 20 + 255) / 256, 256>>>(x);               // 3
    k_scatter1<<<2048, 256>>>(src, dst);                      // 4  <- profiled
    k_gemm1<<<(NN + 127) / 128, 256>>>(W1, b1);               // 5
    k_scatter2<<<2048, 256>>>(src, dst);                      // 6
    {
        dim3 grid((NN + 127) / 128, 2);
        k_gemm2<<<grid, 256>>>(W2, b2, batch);                // 7
    }
    k_ptable<<<(25 * 8 * 64 + 255) / 256, 256>>>(emb, conv_w);// 8
    {
        dim3 grid(NG, 2);
        k_conv<<<grid, 256>>>(seq, conv_b);                   // 9
    }
    k_cnt<<<(NN + 255) / 256, 256>>>(batch);                  // 10
    k_final<<<NG, 256>>>(fc1_w, fc1_b, fc2_w, fc2_b, out);    // 11
}

// round 8
// speedup vs baseline: 1.3603x; 1.0523x over previous
#include <cuda_runtime.h>
#include <cuda_fp16.h>

#define NN 100000
#define NE 1600000
#define NG 512

// ---------------- scratch (device globals; no allocations allowed) ----------
__device__ int   g_cnti[NN];         // int in-degree counts (deg = cnti + 1)
__device__ float g_dinv[NN];         // rsqrt(deg)
__device__ float g_inv[NN];          // 1/deg
__device__ uint4 g_x16v[NN * 10];    // x as __half[NN*80] (cols 78,79 = 0)
__device__ uint4 g_agg1v[NN * 10];   // aggregated x as __half[NN*80]
__device__ uint4 g_h1v[NN * 16];     // relu(gcn1) as __half[NN*128]
__device__ uint4 g_agg2v[NN * 16];   // aggregated h1 as __half[NN*128]
__device__ float g_sums[NG * 256];   // per-graph sums of h2
__device__ float g_cnt[NG];          // per-graph node counts
__device__ float g_ptab[25 * 8 * 64];// precomputed emb@conv_w table [tok][k][o]
__device__ float g_prot[NG * 64];    // protein features after maxpool

// f16x8 reduction helper: p += v * nh (elementwise, 8 halves)
__device__ __forceinline__ void red_f16x8(__half* p, uint4 v, __half2 nh) {
    __half2 h0 = __hmul2(*(const __half2*)&v.x, nh);
    __half2 h1 = __hmul2(*(const __half2*)&v.y, nh);
    __half2 h2 = __hmul2(*(const __half2*)&v.z, nh);
    __half2 h3 = __hmul2(*(const __half2*)&v.w, nh);
    asm volatile("red.global.add.noftz.v4.f16x2 [%0], {%1,%2,%3,%4};"
                 :: "l"(p),
                    "r"(*(const unsigned int*)&h0), "r"(*(const unsigned int*)&h1),
                    "r"(*(const unsigned int*)&h2), "r"(*(const unsigned int*)&h3)
                 : "memory");
}

// ---------------- zero + degree count ----------------------------------------
__global__ void k_zero() {
    int t = blockIdx.x * blockDim.x + threadIdx.x;
    int stride = gridDim.x * blockDim.x;
    for (int i = t; i < NN; i += stride) g_cnti[i] = 0;
    for (int i = t; i < NG * 256; i += stride) g_sums[i] = 0.f;
    for (int i = t; i < NG; i += stride) g_cnt[i] = 0.f;
}

__global__ void k_deg(const int* __restrict__ dst) {
    int t = blockIdx.x * blockDim.x + threadIdx.x;
    if (t < NE) atomicAdd(&g_cnti[dst[t]], 1);
}

// init: x16 = f16(x) zero-padded to 80; agg1 = f16(x/deg); dinv/inv per node.
// NN*10 threads: i = t/10, q = t%10 (8 halves each).
__global__ void k_init1(const float* __restrict__ x) {
    int t = blockIdx.x * blockDim.x + threadIdx.x;
    if (t < NN * 10) {
        int i = t / 10;
        int q = t - i * 10;
        float d = (float)g_cnti[i] + 1.0f;
        float inv = 1.0f / d;
        if (q == 0) {
            g_dinv[i] = rsqrtf(d);
            g_inv[i] = inv;
        }
        float v[8];
        if (q < 9) {
            const float2* xp = (const float2*)(x + (long)i * 78 + q * 8);
#pragma unroll
            for (int j = 0; j < 4; j++) {
                float2 a = xp[j];
                v[2 * j] = a.x; v[2 * j + 1] = a.y;
            }
        } else {
            const float2* xp = (const float2*)(x + (long)i * 78 + 72);
#pragma unroll
            for (int j = 0; j < 3; j++) {
                float2 a = xp[j];
                v[2 * j] = a.x; v[2 * j + 1] = a.y;
            }
            v[6] = 0.f; v[7] = 0.f;
        }
        uint4 raw, agg;
        __half2* rp = (__half2*)&raw;
        __half2* ap = (__half2*)&agg;
#pragma unroll
        for (int j = 0; j < 4; j++) {
            rp[j] = __floats2half2_rn(v[2 * j], v[2 * j + 1]);
            ap[j] = __floats2half2_rn(v[2 * j] * inv, v[2 * j + 1] * inv);
        }
        g_x16v[(long)i * 10 + q] = raw;
        g_agg1v[(long)i * 10 + q] = agg;
    }
}

// ---------------- edge scatter, layer 1 (f16, flat chunk space) -------------
// 80 halves = 160 B per row = 10 x uint4; chunk c <-> (edge c/10, q c%10).
__global__ void k_scatter1(const int* __restrict__ src,
                           const int* __restrict__ dst) {
    const int W = 2048 * 8;                 // total warps
    const int EPW = (NE + W - 1) / W;       // 98 edges per warp
    int w = (blockIdx.x * blockDim.x + threadIdx.x) >> 5;
    int lane = threadIdx.x & 31;
    int e0 = w * EPW;
    if (e0 >= NE) return;
    int ecnt = min(EPW, NE - e0);
    int nchunk = ecnt * 10;
    const __half* x16 = (const __half*)g_x16v;
    __half* agg = (__half*)g_agg1v;

    int c = lane;
    for (; c + 32 < nchunk; c += 64) {
        int c0 = c, c1 = c + 32;
        int le0 = c0 / 10, q0 = c0 - le0 * 10;
        int le1 = c1 / 10, q1 = c1 - le1 * 10;
        int e0i = e0 + le0, e1i = e0 + le1;
        int s0 = __ldg(src + e0i), d0 = __ldg(dst + e0i);
        int s1 = __ldg(src + e1i), d1 = __ldg(dst + e1i);
        float n0 = __ldg(g_dinv + s0) * __ldg(g_dinv + d0);
        float n1 = __ldg(g_dinv + s1) * __ldg(g_dinv + d1);
        uint4 v0 = g_x16v[(long)s0 * 10 + q0];
        uint4 v1 = g_x16v[(long)s1 * 10 + q1];
        red_f16x8(agg + (long)d0 * 80 + q0 * 8, v0, __float2half2_rn(n0));
        red_f16x8(agg + (long)d1 * 80 + q1 * 8, v1, __float2half2_rn(n1));
    }
    for (; c < nchunk; c += 32) {
        int le = c / 10, q = c - le * 10;
        int e = e0 + le;
        int s = __ldg(src + e), d = __ldg(dst + e);
        float nrm = __ldg(g_dinv + s) * __ldg(g_dinv + d);
        uint4 v = g_x16v[(long)s * 10 + q];
        red_f16x8(agg + (long)d * 80 + q * 8, v, __float2half2_rn(nrm));
    }
    (void)x16;
}

// ---------------- GEMM1: h1 = relu(agg1 @ W1 + b1) (f16); agg2 = h1/deg (f16)
__global__ __launch_bounds__(256) void k_gemm1(const float* __restrict__ W1,
                                               const float* __restrict__ b1) {
    __shared__ float sA[128 * 41];
    __shared__ float sB[40 * 128];
    int tid = threadIdx.x;
    int r0 = blockIdx.x * 128;
    int cx = tid & 7, ry = tid >> 3;
    const __half* a1 = (const __half*)g_agg1v;
    float acc[4][16];
#pragma unroll
    for (int i = 0; i < 4; i++)
#pragma unroll
        for (int j = 0; j < 16; j++) acc[i][j] = 0.f;

#pragma unroll 1
    for (int kc = 0; kc < 80; kc += 40) {
        __syncthreads();
        for (int idx = tid; idx < 40 * 128; idx += 256) {
            int k = idx >> 7, c = idx & 127;
            int gk = kc + k;
            sB[idx] = (gk < 78) ? W1[gk * 128 + c] : 0.f;
        }
        for (int idx = tid; idx < 128 * 40; idx += 256) {
            int r = idx / 40, k = idx - r * 40;
            int row = r0 + r;
            sA[r * 41 + k] = (row < NN)
                ? __half2float(a1[(long)row * 80 + kc + k]) : 0.f;
        }
        __syncthreads();
#pragma unroll 8
        for (int k = 0; k < 40; k++) {
            float a[4];
#pragma unroll
            for (int i = 0; i < 4; i++) a[i] = sA[(ry * 4 + i) * 41 + k];
            const float4* B4 = (const float4*)(sB + k * 128);
#pragma unroll
            for (int q = 0; q < 4; q++) {
                float4 b = B4[cx * 4 + q];
#pragma unroll
                for (int i = 0; i < 4; i++) {
                    acc[i][q * 4 + 0] += a[i] * b.x;
                    acc[i][q * 4 + 1] += a[i] * b.y;
                    acc[i][q * 4 + 2] += a[i] * b.z;
                    acc[i][q * 4 + 3] += a[i] * b.w;
                }
            }
        }
    }
    int colb = cx * 16;
    __half* h1 = (__half*)g_h1v;
    __half* a2 = (__half*)g_agg2v;
#pragma unroll
    for (int i = 0; i < 4; i++) {
        int row = r0 + ry * 4 + i;
        if (row < NN) {
            float inv = __ldg(g_inv + row);
#pragma unroll
            for (int q = 0; q < 4; q++) {
                float vx = fmaxf(acc[i][q * 4 + 0] + b1[colb + q * 4 + 0], 0.f);
                float vy = fmaxf(acc[i][q * 4 + 1] + b1[colb + q * 4 + 1], 0.f);
                float vz = fmaxf(acc[i][q * 4 + 2] + b1[colb + q * 4 + 2], 0.f);
                float vw = fmaxf(acc[i][q * 4 + 3] + b1[colb + q * 4 + 3], 0.f);
                __half2 h0 = __floats2half2_rn(vx, vy);
                __half2 h1p = __floats2half2_rn(vz, vw);
                *(__half2*)(h1 + (long)row * 128 + colb + q * 4)     = h0;
                *(__half2*)(h1 + (long)row * 128 + colb + q * 4 + 2) = h1p;
                __half2 a0 = __floats2half2_rn(vx * inv, vy * inv);
                __half2 a1h = __floats2half2_rn(vz * inv, vw * inv);
                *(__half2*)(a2 + (long)row * 128 + colb + q * 4)     = a0;
                *(__half2*)(a2 + (long)row * 128 + colb + q * 4 + 2) = a1h;
            }
        }
    }
}

// ---------------- edge scatter, layer 2 (f16, half-warp per edge) -----------
__global__ void k_scatter2(const int* __restrict__ src,
                           const int* __restrict__ dst) {
    const int W = 2048 * 8;
    const int EPW = (NE + W - 1) / W;       // 98
    int w = (blockIdx.x * blockDim.x + threadIdx.x) >> 5;
    int lane = threadIdx.x & 31;
    int half = lane >> 4;                   // 0 or 1: which edge of the pair
    int q = lane & 15;                      // uint4 index within the row
    int e = w * EPW;
    int end = min(e + EPW, NE);
    if (e >= NE) return;
    const __half* h1 = (const __half*)g_h1v;
    __half* agg = (__half*)g_agg2v;

    for (; e + 3 < end; e += 4) {
        int ea = e + half, eb = e + 2 + half;
        int sa = __ldg(src + ea), da = __ldg(dst + ea);
        int sb = __ldg(src + eb), db = __ldg(dst + eb);
        float na = __ldg(g_dinv + sa) * __ldg(g_dinv + da);
        float nb = __ldg(g_dinv + sb) * __ldg(g_dinv + db);
        uint4 va = ((const uint4*)(h1 + (long)sa * 128))[q];
        uint4 vb = ((const uint4*)(h1 + (long)sb * 128))[q];
        red_f16x8(agg + (long)da * 128 + q * 8, va, __float2half2_rn(na));
        red_f16x8(agg + (long)db * 128 + q * 8, vb, __float2half2_rn(nb));
    }
    for (; e < end; e += 2) {
        if (e + half < end) {
            int ei = e + half;
            int s = __ldg(src + ei), d = __ldg(dst + ei);
            float nrm = __ldg(g_dinv + s) * __ldg(g_dinv + d);
            uint4 v = ((const uint4*)(h1 + (long)s * 128))[q];
            red_f16x8(agg + (long)d * 128 + q * 8, v, __float2half2_rn(nrm));
        }
    }
}

// ---------------- GEMM2 + fused mean-pool epilogue ---------------------------
__global__ __launch_bounds__(256) void k_gemm2(const float* __restrict__ W2,
                                               const float* __restrict__ b2,
                                               const int* __restrict__ batch) {
    __shared__ float sA[128 * 33];
    __shared__ float sB[32 * 128];
    int tid = threadIdx.x;
    int r0 = blockIdx.x * 128;
    int cb = blockIdx.y * 128;
    int cx = tid & 7, ry = tid >> 3;
    const __half* a2 = (const __half*)g_agg2v;
    float acc[4][16];
#pragma unroll
    for (int i = 0; i < 4; i++)
#pragma unroll
        for (int j = 0; j < 16; j++) acc[i][j] = 0.f;

#pragma unroll 1
    for (int kc = 0; kc < 128; kc += 32) {
        __syncthreads();
        for (int idx = tid; idx < 32 * 128; idx += 256) {
            int k = idx >> 7, c = idx & 127;
            sB[idx] = W2[(kc + k) * 256 + cb + c];
        }
        for (int idx = tid; idx < 128 * 32; idx += 256) {
            int r = idx >> 5, k = idx & 31;
            int row = r0 + r;
            sA[r * 33 + k] = (row < NN)
                ? __half2float(a2[(long)row * 128 + kc + k]) : 0.f;
        }
        __syncthreads();
#pragma unroll 8
        for (int k = 0; k < 32; k++) {
            float a[4];
#pragma unroll
            for (int i = 0; i < 4; i++) a[i] = sA[(ry * 4 + i) * 33 + k];
            const float4* B4 = (const float4*)(sB + k * 128);
#pragma unroll
            for (int q = 0; q < 4; q++) {
                float4 b = B4[cx * 4 + q];
#pragma unroll
                for (int i = 0; i < 4; i++) {
                    acc[i][q * 4 + 0] += a[i] * b.x;
                    acc[i][q * 4 + 1] += a[i] * b.y;
                    acc[i][q * 4 + 2] += a[i] * b.z;
                    acc[i][q * 4 + 3] += a[i] * b.w;
                }
            }
        }
    }
    int colb = cx * 16;
#pragma unroll
    for (int i = 0; i < 4; i++) {
        int row = r0 + ry * 4 + i;
        if (row < NN) {
            int g = batch[row];
            float* base = g_sums + g * 256 + cb + colb;
#pragma unroll
            for (int q = 0; q < 4; q++) {
                float vx = fmaxf(acc[i][q * 4 + 0] + b2[cb + colb + q * 4 + 0], 0.f);
                float vy = fmaxf(acc[i][q * 4 + 1] + b2[cb + colb + q * 4 + 1], 0.f);
                float vz = fmaxf(acc[i][q * 4 + 2] + b2[cb + colb + q * 4 + 2], 0.f);
                float vw = fmaxf(acc[i][q * 4 + 3] + b2[cb + colb + q * 4 + 3], 0.f);
                asm volatile("red.global.add.v4.f32 [%0], {%1,%2,%3,%4};"
                             :: "l"(base + q * 4), "f"(vx), "f"(vy), "f"(vz), "f"(vw)
                             : "memory");
            }
        }
    }
}

// ---------------- protein path -----------------------------------------------
__global__ void k_ptable(const float* __restrict__ emb,
                         const float* __restrict__ conv_w) {
    int idx = blockIdx.x * blockDim.x + threadIdx.x;
    if (idx < 25 * 8 * 64) {
        int o = idx & 63;
        int k = (idx >> 6) & 7;
        int tok = idx >> 9;
        float s = 0.f;
#pragma unroll 4
        for (int i = 0; i < 128; i++)
            s += emb[tok * 128 + i] * conv_w[o * 1024 + i * 8 + k];
        g_ptab[tok * 512 + k * 64 + o] = s;
    }
}

__global__ __launch_bounds__(256) void k_conv(const int* __restrict__ seq,
                                              const float* __restrict__ conv_b) {
    __shared__ float2 stab[25 * 8 * 16];   // [tok][k][chan-pair]
    __shared__ int sseq[1024];
    __shared__ float2 sred[256];
    int tid = threadIdx.x;
    int b = blockIdx.x;
    int co = blockIdx.y * 32;

    for (int idx = tid; idx < 1024; idx += 256) sseq[idx] = seq[b * 1024 + idx];
    for (int idx = tid; idx < 25 * 8 * 16; idx += 256) {
        int p = idx & 15;
        int kk = (idx >> 4) & 7;
        int tok = idx >> 7;
        stab[idx] = make_float2(g_ptab[tok * 512 + kk * 64 + co + 2 * p],
                                g_ptab[tok * 512 + kk * 64 + co + 2 * p + 1]);
    }
    __syncthreads();

    int p = tid & 15;
    int phase = tid >> 4;
    float2 m = make_float2(-1e30f, -1e30f);
    for (int l = phase; l < 1017; l += 16) {
        float sx = 0.f, sy = 0.f;
#pragma unroll
        for (int k = 0; k < 8; k++) {
            float2 v = stab[(sseq[l + k] * 8 + k) * 16 + p];
            sx += v.x; sy += v.y;
        }
        m.x = fmaxf(m.x, sx);
        m.y = fmaxf(m.y, sy);
    }
    sred[tid] = m;
    __syncthreads();
    if (tid < 16) {
        float2 mm = sred[tid];
#pragma unroll
        for (int g = 1; g < 16; g++) {
            float2 v = sred[g * 16 + tid];
            mm.x = fmaxf(mm.x, v.x);
            mm.y = fmaxf(mm.y, v.y);
        }
        g_prot[b * 64 + co + 2 * tid]     = fmaxf(mm.x + conv_b[co + 2 * tid], 0.f);
        g_prot[b * 64 + co + 2 * tid + 1] = fmaxf(mm.y + conv_b[co + 2 * tid + 1], 0.f);
    }
}

__global__ void k_cnt(const int* __restrict__ batch) {
    int t = blockIdx.x * blockDim.x + threadIdx.x;
    if (t < NN) atomicAdd(&g_cnt[batch[t]], 1.0f);
}

// ---------------- final MLP ---------------------------------------------------
__global__ __launch_bounds__(256) void k_final(const float* __restrict__ fc1_w,
                                               const float* __restrict__ fc1_b,
                                               const float* __restrict__ fc2_w,
                                               const float* __restrict__ fc2_b,
                                               float* __restrict__ out) {
    __shared__ float comb[320];
    __shared__ float sred[256];
    int tid = threadIdx.x;
    int b = blockIdx.x;
    float invc = 1.0f / fmaxf(g_cnt[b], 1.0f);
    if (tid < 256) comb[tid] = g_sums[b * 256 + tid] * invc;
    if (tid < 64) comb[256 + tid] = g_prot[b * 64 + tid];
    __syncthreads();

    float part = 0.f;
#pragma unroll
    for (int rep = 0; rep < 2; rep++) {
        int o = tid + rep * 256;
        float acc = fc1_b[o];
#pragma unroll 4
        for (int j = 0; j < 320; j++)
            acc += comb[j] * fc1_w[j * 512 + o];
        part += fmaxf(acc, 0.f) * fc2_w[o];
    }
    sred[tid] = part;
    __syncthreads();
    for (int s = 128; s > 0; s >>= 1) {
        if (tid < s) sred[tid] += sred[tid + s];
        __syncthreads();
    }
    if (tid == 0) out[b] = sred[0] + fc2_b[0];
}

// ---------------- launch ------------------------------------------------------
extern "C" void kernel_launch(void* const* d_in, const int* in_sizes, int n_in,
                              void* d_out, int out_size) {
    const float* x       = (const float*)d_in[0];
    const int*   ei      = (const int*)  d_in[1];   // [2, NE]
    const int*   batch   = (const int*)  d_in[2];
    const int*   seq     = (const int*)  d_in[3];   // [NG, 1024]
    const float* W1      = (const float*)d_in[4];
    const float* b1      = (const float*)d_in[5];
    const float* W2      = (const float*)d_in[6];
    const float* b2      = (const float*)d_in[7];
    const float* emb     = (const float*)d_in[8];
    const float* conv_w  = (const float*)d_in[9];
    const float* conv_b  = (const float*)d_in[10];
    const float* fc1_w   = (const float*)d_in[11];
    const float* fc1_b   = (const float*)d_in[12];
    const float* fc2_w   = (const float*)d_in[13];
    const float* fc2_b   = (const float*)d_in[14];
    float* out = (float*)d_out;

    const int* src = ei;
    const int* dst = ei + NE;

    k_zero<<<512, 256>>>();                                   // 1
    k_deg<<<(NE + 255) / 256, 256>>>(dst);                    // 2
    k_init1<<<(NN * 10 + 255) / 256, 256>>>(x);               // 3
    k_scatter1<<<2048, 256>>>(src, dst);                      // 4  <- profiled
    k_gemm1<<<(NN + 127) / 128, 256>>>(W1, b1);               // 5
    k_scatter2<<<2048, 256>>>(src, dst);                      // 6
    {
        dim3 grid((NN + 127) / 128, 2);
        k_gemm2<<<grid, 256>>>(W2, b2, batch);                // 7
    }
    k_ptable<<<(25 * 8 * 64 + 255) / 256, 256>>>(emb, conv_w);// 8
    {
        dim3 grid(NG, 2);
        k_conv<<<grid, 256>>>(seq, conv_b);                   // 9
    }
    k_cnt<<<(NN + 255) / 256, 256>>>(batch);                  // 10
    k_final<<<NG, 256>>>(fc1_w, fc1_b, fc2_w, fc2_b, out);    // 11
}

// round 10
// speedup vs baseline: 2.9899x; 2.1980x over previous
#include <cuda_runtime.h>
#include <cuda_fp16.h>
#include <mma.h>

using namespace nvcuda;

#define NN 100000
#define NE 1600000
#define NG 512

// ---------------- scratch (device globals; no allocations allowed) ----------
__device__ int    g_cnti[NN];         // int in-degree counts (deg = cnti + 1)
__device__ float  g_dinv[NN];         // rsqrt(deg)
__device__ float  g_inv[NN];          // 1/deg
__device__ uint4  g_x16v[NN * 10];    // x as __half[NN*80] (cols 78,79 = 0)
__device__ uint4  g_agg1v[NN * 10];   // aggregated x as __half[NN*80]
__device__ uint4  g_h1v[NN * 16];     // relu(gcn1) as __half[NN*128]
__device__ uint4  g_agg2v[NN * 16];   // aggregated h1 as __half[NN*128]
__device__ __half g_w1h[80 * 128];    // W1 as f16, K padded to 80
__device__ __half g_w2h[128 * 256];   // W2 as f16
__device__ float  g_sums[NG * 256];   // per-graph sums of h2
__device__ float  g_cnt[NG];          // per-graph node counts
__device__ float  g_ptab[25 * 8 * 64];// precomputed emb@conv_w table [tok][k][o]
__device__ float  g_prot[NG * 64];    // protein features after maxpool

// f16x8 reduction helper: p += v * nh (elementwise, 8 halves)
__device__ __forceinline__ void red_f16x8(__half* p, uint4 v, __half2 nh) {
    __half2 h0 = __hmul2(*(const __half2*)&v.x, nh);
    __half2 h1 = __hmul2(*(const __half2*)&v.y, nh);
    __half2 h2 = __hmul2(*(const __half2*)&v.z, nh);
    __half2 h3 = __hmul2(*(const __half2*)&v.w, nh);
    asm volatile("red.global.add.noftz.v4.f16x2 [%0], {%1,%2,%3,%4};"
                 :: "l"(p),
                    "r"(*(const unsigned int*)&h0), "r"(*(const unsigned int*)&h1),
                    "r"(*(const unsigned int*)&h2), "r"(*(const unsigned int*)&h3)
                 : "memory");
}

// ---------------- zero + degree count ----------------------------------------
__global__ void k_zero() {
    int t = blockIdx.x * blockDim.x + threadIdx.x;
    int stride = gridDim.x * blockDim.x;
    for (int i = t; i < NN; i += stride) g_cnti[i] = 0;
    for (int i = t; i < NG * 256; i += stride) g_sums[i] = 0.f;
    for (int i = t; i < NG; i += stride) g_cnt[i] = 0.f;
}

__global__ void k_deg(const int* __restrict__ dst) {
    int t = blockIdx.x * blockDim.x + threadIdx.x;
    if (t < NE) atomicAdd(&g_cnti[dst[t]], 1);
}

// init: x16 = f16(x) zero-padded to 80; agg1 = f16(x/deg); dinv/inv per node.
__global__ void k_init1(const float* __restrict__ x) {
    int t = blockIdx.x * blockDim.x + threadIdx.x;
    if (t < NN * 10) {
        int i = t / 10;
        int q = t - i * 10;
        float d = (float)g_cnti[i] + 1.0f;
        float inv = 1.0f / d;
        if (q == 0) {
            g_dinv[i] = rsqrtf(d);
            g_inv[i] = inv;
        }
        float v[8];
        if (q < 9) {
            const float2* xp = (const float2*)(x + (long)i * 78 + q * 8);
#pragma unroll
            for (int j = 0; j < 4; j++) {
                float2 a = xp[j];
                v[2 * j] = a.x; v[2 * j + 1] = a.y;
            }
        } else {
            const float2* xp = (const float2*)(x + (long)i * 78 + 72);
#pragma unroll
            for (int j = 0; j < 3; j++) {
                float2 a = xp[j];
                v[2 * j] = a.x; v[2 * j + 1] = a.y;
            }
            v[6] = 0.f; v[7] = 0.f;
        }
        uint4 raw, agg;
        __half2* rp = (__half2*)&raw;
        __half2* ap = (__half2*)&agg;
#pragma unroll
        for (int j = 0; j < 4; j++) {
            rp[j] = __floats2half2_rn(v[2 * j], v[2 * j + 1]);
            ap[j] = __floats2half2_rn(v[2 * j] * inv, v[2 * j + 1] * inv);
        }
        g_x16v[(long)i * 10 + q] = raw;
        g_agg1v[(long)i * 10 + q] = agg;
    }
}

// convert weights to f16 (W1 padded to 80 rows)
__global__ void k_wconv(const float* __restrict__ W1,
                        const float* __restrict__ W2) {
    int t = blockIdx.x * blockDim.x + threadIdx.x;
    if (t < 80 * 128) {
        int k = t >> 7;
        g_w1h[t] = __float2half((k < 78) ? W1[t] : 0.f);
    }
    if (t < 128 * 256) {
        g_w2h[t] = __float2half(W2[t]);
    }
}

// ---------------- edge scatter, layer 1 (f16, flat chunk space) -------------
__global__ void k_scatter1(const int* __restrict__ src,
                           const int* __restrict__ dst) {
    const int W = 2048 * 8;                 // total warps
    const int EPW = (NE + W - 1) / W;       // 98 edges per warp
    int w = (blockIdx.x * blockDim.x + threadIdx.x) >> 5;
    int lane = threadIdx.x & 31;
    int e0 = w * EPW;
    if (e0 >= NE) return;
    int ecnt = min(EPW, NE - e0);
    int nchunk = ecnt * 10;
    __half* agg = (__half*)g_agg1v;

    int c = lane;
    for (; c + 32 < nchunk; c += 64) {
        int c0 = c, c1 = c + 32;
        int le0 = c0 / 10, q0 = c0 - le0 * 10;
        int le1 = c1 / 10, q1 = c1 - le1 * 10;
        int e0i = e0 + le0, e1i = e0 + le1;
        int s0 = __ldg(src + e0i), d0 = __ldg(dst + e0i);
        int s1 = __ldg(src + e1i), d1 = __ldg(dst + e1i);
        float n0 = __ldg(g_dinv + s0) * __ldg(g_dinv + d0);
        float n1 = __ldg(g_dinv + s1) * __ldg(g_dinv + d1);
        uint4 v0 = g_x16v[(long)s0 * 10 + q0];
        uint4 v1 = g_x16v[(long)s1 * 10 + q1];
        red_f16x8(agg + (long)d0 * 80 + q0 * 8, v0, __float2half2_rn(n0));
        red_f16x8(agg + (long)d1 * 80 + q1 * 8, v1, __float2half2_rn(n1));
    }
    for (; c < nchunk; c += 32) {
        int le = c / 10, q = c - le * 10;
        int e = e0 + le;
        int s = __ldg(src + e), d = __ldg(dst + e);
        float nrm = __ldg(g_dinv + s) * __ldg(g_dinv + d);
        uint4 v = g_x16v[(long)s * 10 + q];
        red_f16x8(agg + (long)d * 80 + q * 8, v, __float2half2_rn(nrm));
    }
}

// ---------------- GEMM1 (tensor cores): h1 = relu(agg1@W1 + b1); agg2=h1/deg
// Block: 256 thr = 8 warps (4x2), tile 128x128, K=80 single shot.
__global__ __launch_bounds__(256) void k_gemm1(const float* __restrict__ b1) {
    __shared__ union {
        struct {
            uint4 a[128 * 11];   // f16 [128][88]
            uint4 b[80 * 17];    // f16 [80][136]
        } ld;
        float stg[128 * 68];
    } sm;
    int tid = threadIdx.x;
    int r0 = blockIdx.x * 128;
    int wid = tid >> 5;
    int wm = wid >> 1;      // 0..3
    int wn = wid & 1;       // 0..1

    const uint4 zero4 = make_uint4(0, 0, 0, 0);
    for (int idx = tid; idx < 128 * 10; idx += 256) {
        int r = idx / 10, u = idx - r * 10;
        int row = r0 + r;
        sm.ld.a[r * 11 + u] = (row < NN) ? g_agg1v[(long)row * 10 + u] : zero4;
    }
    const uint4* w1v = (const uint4*)g_w1h;
    for (int idx = tid; idx < 80 * 16; idx += 256) {
        int k = idx >> 4, u = idx & 15;
        sm.ld.b[k * 17 + u] = w1v[k * 16 + u];
    }
    __syncthreads();

    wmma::fragment<wmma::accumulator, 16, 16, 16, float> cf[2][4];
#pragma unroll
    for (int i = 0; i < 2; i++)
#pragma unroll
        for (int j = 0; j < 4; j++) wmma::fill_fragment(cf[i][j], 0.f);

    const __half* As = (const __half*)sm.ld.a;
    const __half* Bs = (const __half*)sm.ld.b;
#pragma unroll
    for (int k = 0; k < 80; k += 16) {
        wmma::fragment<wmma::matrix_a, 16, 16, 16, __half, wmma::row_major> af[2];
        wmma::load_matrix_sync(af[0], As + (wm * 32) * 88 + k, 88);
        wmma::load_matrix_sync(af[1], As + (wm * 32 + 16) * 88 + k, 88);
        wmma::fragment<wmma::matrix_b, 16, 16, 16, __half, wmma::row_major> bf[4];
#pragma unroll
        for (int j = 0; j < 4; j++)
            wmma::load_matrix_sync(bf[j], Bs + k * 136 + wn * 64 + j * 16, 136);
#pragma unroll
        for (int i = 0; i < 2; i++)
#pragma unroll
            for (int j = 0; j < 4; j++)
                wmma::mma_sync(cf[i][j], af[i], bf[j], cf[i][j]);
    }
    __syncthreads();

    __half* h1 = (__half*)g_h1v;
    __half* a2 = (__half*)g_agg2v;
#pragma unroll 1
    for (int ph = 0; ph < 2; ph++) {
        if (wn == ph) {
#pragma unroll
            for (int i = 0; i < 2; i++)
#pragma unroll
                for (int j = 0; j < 4; j++)
                    wmma::store_matrix_sync(
                        sm.stg + (wm * 32 + i * 16) * 68 + j * 16,
                        cf[i][j], 68, wmma::mem_row_major);
        }
        __syncthreads();
        for (int idx = tid; idx < 128 * 32; idx += 256) {
            int r = idx >> 5;
            int cp = idx & 31;
            int row = r0 + r;
            if (row < NN) {
                int col = ph * 64 + cp * 2;          // global column
                float v0 = sm.stg[r * 68 + cp * 2];          // local read
                float v1 = sm.stg[r * 68 + cp * 2 + 1];
                v0 = fmaxf(v0 + b1[col], 0.f);
                v1 = fmaxf(v1 + b1[col + 1], 0.f);
                float inv = __ldg(g_inv + row);
                *(__half2*)(h1 + (long)row * 128 + col) = __floats2half2_rn(v0, v1);
                *(__half2*)(a2 + (long)row * 128 + col) =
                    __floats2half2_rn(v0 * inv, v1 * inv);
            }
        }
        __syncthreads();
    }
}

// ---------------- edge scatter, layer 2 (f16, half-warp per edge) -----------
__global__ void k_scatter2(const int* __restrict__ src,
                           const int* __restrict__ dst) {
    const int W = 2048 * 8;
    const int EPW = (NE + W - 1) / W;       // 98
    int w = (blockIdx.x * blockDim.x + threadIdx.x) >> 5;
    int lane = threadIdx.x & 31;
    int half = lane >> 4;
    int q = lane & 15;
    int e = w * EPW;
    int end = min(e + EPW, NE);
    if (e >= NE) return;
    const __half* h1 = (const __half*)g_h1v;
    __half* agg = (__half*)g_agg2v;

    for (; e + 3 < end; e += 4) {
        int ea = e + half, eb = e + 2 + half;
        int sa = __ldg(src + ea), da = __ldg(dst + ea);
        int sb = __ldg(src + eb), db = __ldg(dst + eb);
        float na = __ldg(g_dinv + sa) * __ldg(g_dinv + da);
        float nb = __ldg(g_dinv + sb) * __ldg(g_dinv + db);
        uint4 va = ((const uint4*)(h1 + (long)sa * 128))[q];
        uint4 vb = ((const uint4*)(h1 + (long)sb * 128))[q];
        red_f16x8(agg + (long)da * 128 + q * 8, va, __float2half2_rn(na));
        red_f16x8(agg + (long)db * 128 + q * 8, vb, __float2half2_rn(nb));
    }
    for (; e < end; e += 2) {
        if (e + half < end) {
            int ei = e + half;
            int s = __ldg(src + ei), d = __ldg(dst + ei);
            float nrm = __ldg(g_dinv + s) * __ldg(g_dinv + d);
            uint4 v = ((const uint4*)(h1 + (long)s * 128))[q];
            red_f16x8(agg + (long)d * 128 + q * 8, v, __float2half2_rn(nrm));
        }
    }
}

// ---------------- GEMM2 (tensor cores) + fused mean-pool epilogue -----------
// grid (ceil(NN/128), 2); block 256 thr = 8 warps (4x2); tile 128x128; K=128 in 2 chunks.
__global__ __launch_bounds__(256) void k_gemm2(const float* __restrict__ b2,
                                               const int* __restrict__ batch) {
    __shared__ union {
        struct {
            uint4 a[128 * 9];    // f16 [128][72] (K chunk 64)
            uint4 b[64 * 17];    // f16 [64][136]
        } ld;
        float stg[128 * 68];
    } sm;
    int tid = threadIdx.x;
    int r0 = blockIdx.x * 128;
    int cb = blockIdx.y * 128;
    int wid = tid >> 5;
    int wm = wid >> 1;
    int wn = wid & 1;

    wmma::fragment<wmma::accumulator, 16, 16, 16, float> cf[2][4];
#pragma unroll
    for (int i = 0; i < 2; i++)
#pragma unroll
        for (int j = 0; j < 4; j++) wmma::fill_fragment(cf[i][j], 0.f);

    const uint4 zero4 = make_uint4(0, 0, 0, 0);
    const uint4* w2v = (const uint4*)g_w2h;   // rows of 32 uint4 (256 halves)
    const __half* As = (const __half*)sm.ld.a;
    const __half* Bs = (const __half*)sm.ld.b;

#pragma unroll 1
    for (int kc = 0; kc < 128; kc += 64) {
        __syncthreads();
        for (int idx = tid; idx < 128 * 8; idx += 256) {
            int r = idx >> 3, u = idx & 7;
            int row = r0 + r;
            sm.ld.a[r * 9 + u] =
                (row < NN) ? g_agg2v[(long)row * 16 + (kc >> 3) + u] : zero4;
        }
        for (int idx = tid; idx < 64 * 16; idx += 256) {
            int k = idx >> 4, u = idx & 15;
            sm.ld.b[k * 17 + u] = w2v[(kc + k) * 32 + (cb >> 3) + u];
        }
        __syncthreads();
#pragma unroll
        for (int k = 0; k < 64; k += 16) {
            wmma::fragment<wmma::matrix_a, 16, 16, 16, __half, wmma::row_major> af[2];
            wmma::load_matrix_sync(af[0], As + (wm * 32) * 72 + k, 72);
            wmma::load_matrix_sync(af[1], As + (wm * 32 + 16) * 72 + k, 72);
            wmma::fragment<wmma::matrix_b, 16, 16, 16, __half, wmma::row_major> bf[4];
#pragma unroll
            for (int j = 0; j < 4; j++)
                wmma::load_matrix_sync(bf[j], Bs + k * 136 + wn * 64 + j * 16, 136);
#pragma unroll
            for (int i = 0; i < 2; i++)
#pragma unroll
                for (int j = 0; j < 4; j++)
                    wmma::mma_sync(cf[i][j], af[i], bf[j], cf[i][j]);
        }
    }
    __syncthreads();

#pragma unroll 1
    for (int ph = 0; ph < 2; ph++) {
        if (wn == ph) {
#pragma unroll
            for (int i = 0; i < 2; i++)
#pragma unroll
                for (int j = 0; j < 4; j++)
                    wmma::store_matrix_sync(
                        sm.stg + (wm * 32 + i * 16) * 68 + j * 16,
                        cf[i][j], 68, wmma::mem_row_major);
        }
        __syncthreads();
        for (int idx = tid; idx < 128 * 16; idx += 256) {
            int r = idx >> 4;
            int qd = idx & 15;
            int row = r0 + r;
            if (row < NN) {
                int lcol = qd * 4;                   // local staged column
                int gcol = cb + ph * 64 + lcol;      // global output column
                float v0 = fmaxf(sm.stg[r * 68 + lcol + 0] + b2[gcol + 0], 0.f);
                float v1 = fmaxf(sm.stg[r * 68 + lcol + 1] + b2[gcol + 1], 0.f);
                float v2 = fmaxf(sm.stg[r * 68 + lcol + 2] + b2[gcol + 2], 0.f);
                float v3 = fmaxf(sm.stg[r * 68 + lcol + 3] + b2[gcol + 3], 0.f);
                int g = __ldg(batch + row);
                float* p = g_sums + g * 256 + gcol;
                asm volatile("red.global.add.v4.f32 [%0], {%1,%2,%3,%4};"
                             :: "l"(p), "f"(v0), "f"(v1), "f"(v2), "f"(v3)
                             : "memory");
            }
        }
        __syncthreads();
    }
}

// ---------------- protein path -----------------------------------------------
__global__ void k_ptable(const float* __restrict__ emb,
                         const float* __restrict__ conv_w) {
    int idx = blockIdx.x * blockDim.x + threadIdx.x;
    if (idx < 25 * 8 * 64) {
        int o = idx & 63;
        int k = (idx >> 6) & 7;
        int tok = idx >> 9;
        float s = 0.f;
#pragma unroll 4
        for (int i = 0; i < 128; i++)
            s += emb[tok * 128 + i] * conv_w[o * 1024 + i * 8 + k];
        g_ptab[tok * 512 + k * 64 + o] = s;
    }
}

__global__ __launch_bounds__(256) void k_conv(const int* __restrict__ seq,
                                              const float* __restrict__ conv_b) {
    __shared__ float2 stab[25 * 8 * 16];   // [tok][k][chan-pair]
    __shared__ int sseq[1024];
    __shared__ float2 sred[256];
    int tid = threadIdx.x;
    int b = blockIdx.x;
    int co = blockIdx.y * 32;

    for (int idx = tid; idx < 1024; idx += 256) sseq[idx] = seq[b * 1024 + idx];
    for (int idx = tid; idx < 25 * 8 * 16; idx += 256) {
        int p = idx & 15;
        int kk = (idx >> 4) & 7;
        int tok = idx >> 7;
        stab[idx] = make_float2(g_ptab[tok * 512 + kk * 64 + co + 2 * p],
                                g_ptab[tok * 512 + kk * 64 + co + 2 * p + 1]);
    }
    __syncthreads();

    int p = tid & 15;
    int phase = tid >> 4;
    float2 m = make_float2(-1e30f, -1e30f);
    for (int l = phase; l < 1017; l += 16) {
        float sx = 0.f, sy = 0.f;
#pragma unroll
        for (int k = 0; k < 8; k++) {
            float2 v = stab[(sseq[l + k] * 8 + k) * 16 + p];
            sx += v.x; sy += v.y;
        }
        m.x = fmaxf(m.x, sx);
        m.y = fmaxf(m.y, sy);
    }
    sred[tid] = m;
    __syncthreads();
    if (tid < 16) {
        float2 mm = sred[tid];
#pragma unroll
        for (int g = 1; g < 16; g++) {
            float2 v = sred[g * 16 + tid];
            mm.x = fmaxf(mm.x, v.x);
            mm.y = fmaxf(mm.y, v.y);
        }
        g_prot[b * 64 + co + 2 * tid]     = fmaxf(mm.x + conv_b[co + 2 * tid], 0.f);
        g_prot[b * 64 + co + 2 * tid + 1] = fmaxf(mm.y + conv_b[co + 2 * tid + 1], 0.f);
    }
}

__global__ void k_cnt(const int* __restrict__ batch) {
    int t = blockIdx.x * blockDim.x + threadIdx.x;
    if (t < NN) atomicAdd(&g_cnt[batch[t]], 1.0f);
}

// ---------------- final MLP ---------------------------------------------------
__global__ __launch_bounds__(256) void k_final(const float* __restrict__ fc1_w,
                                               const float* __restrict__ fc1_b,
                                               const float* __restrict__ fc2_w,
                                               const float* __restrict__ fc2_b,
                                               float* __restrict__ out) {
    __shared__ float comb[320];
    __shared__ float sred[256];
    int tid = threadIdx.x;
    int b = blockIdx.x;
    float invc = 1.0f / fmaxf(g_cnt[b], 1.0f);
    if (tid < 256) comb[tid] = g_sums[b * 256 + tid] * invc;
    if (tid < 64) comb[256 + tid] = g_prot[b * 64 + tid];
    __syncthreads();

    float part = 0.f;
#pragma unroll
    for (int rep = 0; rep < 2; rep++) {
        int o = tid + rep * 256;
        float acc = fc1_b[o];
#pragma unroll 4
        for (int j = 0; j < 320; j++)
            acc += comb[j] * fc1_w[j * 512 + o];
        part += fmaxf(acc, 0.f) * fc2_w[o];
    }
    sred[tid] = part;
    __syncthreads();
    for (int s = 128; s > 0; s >>= 1) {
        if (tid < s) sred[tid] += sred[tid + s];
        __syncthreads();
    }
    if (tid == 0) out[b] = sred[0] + fc2_b[0];
}

// ---------------- launch ------------------------------------------------------
extern "C" void kernel_launch(void* const* d_in, const int* in_sizes, int n_in,
                              void* d_out, int out_size) {
    const float* x       = (const float*)d_in[0];
    const int*   ei      = (const int*)  d_in[1];   // [2, NE]
    const int*   batch   = (const int*)  d_in[2];
    const int*   seq     = (const int*)  d_in[3];   // [NG, 1024]
    const float* W1      = (const float*)d_in[4];
    const float* b1      = (const float*)d_in[5];
    const float* W2      = (const float*)d_in[6];
    const float* b2      = (const float*)d_in[7];
    const float* emb     = (const float*)d_in[8];
    const float* conv_w  = (const float*)d_in[9];
    const float* conv_b  = (const float*)d_in[10];
    const float* fc1_w   = (const float*)d_in[11];
    const float* fc1_b   = (const float*)d_in[12];
    const float* fc2_w   = (const float*)d_in[13];
    const float* fc2_b   = (const float*)d_in[14];
    float* out = (float*)d_out;

    const int* src = ei;
    const int* dst = ei + NE;

    k_zero<<<512, 256>>>();                                   // 1
    k_deg<<<(NE + 255) / 256, 256>>>(dst);                    // 2
    k_init1<<<(NN * 10 + 255) / 256, 256>>>(x);               // 3
    k_scatter1<<<2048, 256>>>(src, dst);                      // 4  <- profiled
    k_wconv<<<(128 * 256 + 255) / 256, 256>>>(W1, W2);        // 5
    k_gemm1<<<(NN + 127) / 128, 256>>>(b1);                   // 6
    k_scatter2<<<2048, 256>>>(src, dst);                      // 7
    {
        dim3 grid((NN + 127) / 128, 2);
        k_gemm2<<<grid, 256>>>(b2, batch);                    // 8
    }
    k_ptable<<<(25 * 8 * 64 + 255) / 256, 256>>>(emb, conv_w);// 9
    {
        dim3 grid(NG, 2);
        k_conv<<<grid, 256>>>(seq, conv_b);                   // 10
    }
    k_cnt<<<(NN + 255) / 256, 256>>>(batch);                  // 11
    k_final<<<NG, 256>>>(fc1_w, fc1_b, fc2_w, fc2_b, out);    // 12
}

// round 11
// speedup vs baseline: 3.0282x; 1.0128x over previous
#include <cuda_runtime.h>
#include <cuda_fp16.h>
#include <cuda_fp8.h>
#include <mma.h>

using namespace nvcuda;

#define NN 100000
#define NE 1600000
#define NG 512

// ---------------- scratch (device globals; no allocations allowed) ----------
__device__ int    g_cnti[NN];         // int in-degree counts (deg = cnti + 1)
__device__ float  g_dinv[NN];         // rsqrt(deg)
__device__ float  g_inv[NN];          // 1/deg
__device__ uint4  g_x16v[NN * 10];    // x as __half[NN*80] (cols 78,79 = 0)
__device__ uint4  g_agg1v[NN * 10];   // aggregated x as __half[NN*80]
__device__ uint2  g_h1qv[NN * 16];    // relu(gcn1) as fp8 e4m3 [NN*128]
__device__ uint4  g_agg2v[NN * 16];   // aggregated h1 as __half[NN*128]
__device__ __half g_w1h[80 * 128];    // W1 as f16, K padded to 80
__device__ __half g_w2h[128 * 256];   // W2 as f16
__device__ __half g_fc1h[320 * 512];  // fc1_w as f16
__device__ __half g_fc2h[512];        // fc2_w as f16
__device__ float  g_sums[NG * 256];   // per-graph sums of h2
__device__ float  g_cnt[NG];          // per-graph node counts
__device__ float  g_ptab[25 * 8 * 64];// precomputed emb@conv_w table [tok][k][o]
__device__ float  g_prot[NG * 64];    // protein features after maxpool

// f16x8 reduction helper: p += v * nh (elementwise, 8 halves)
__device__ __forceinline__ void red_f16x8(__half* p, uint4 v, __half2 nh) {
    __half2 h0 = __hmul2(*(const __half2*)&v.x, nh);
    __half2 h1 = __hmul2(*(const __half2*)&v.y, nh);
    __half2 h2 = __hmul2(*(const __half2*)&v.z, nh);
    __half2 h3 = __hmul2(*(const __half2*)&v.w, nh);
    asm volatile("red.global.add.noftz.v4.f16x2 [%0], {%1,%2,%3,%4};"
                 :: "l"(p),
                    "r"(*(const unsigned int*)&h0), "r"(*(const unsigned int*)&h1),
                    "r"(*(const unsigned int*)&h2), "r"(*(const unsigned int*)&h3)
                 : "memory");
}

// 8 fp8(e4m3) packed in uint2 -> 8 f16 packed in uint4
__device__ __forceinline__ uint4 fp8x8_to_f16x8(uint2 qv) {
    uint4 r;
    __half2_raw a0 = __nv_cvt_fp8x2_to_halfraw2(
        (__nv_fp8x2_storage_t)(qv.x & 0xFFFF), __NV_E4M3);
    __half2_raw a1 = __nv_cvt_fp8x2_to_halfraw2(
        (__nv_fp8x2_storage_t)(qv.x >> 16), __NV_E4M3);
    __half2_raw a2 = __nv_cvt_fp8x2_to_halfraw2(
        (__nv_fp8x2_storage_t)(qv.y & 0xFFFF), __NV_E4M3);
    __half2_raw a3 = __nv_cvt_fp8x2_to_halfraw2(
        (__nv_fp8x2_storage_t)(qv.y >> 16), __NV_E4M3);
    r.x = *(unsigned int*)&a0;
    r.y = *(unsigned int*)&a1;
    r.z = *(unsigned int*)&a2;
    r.w = *(unsigned int*)&a3;
    return r;
}

// ---------------- zero + degree count ----------------------------------------
__global__ void k_zero() {
    int t = blockIdx.x * blockDim.x + threadIdx.x;
    int stride = gridDim.x * blockDim.x;
    for (int i = t; i < NN; i += stride) g_cnti[i] = 0;
    for (int i = t; i < NG * 256; i += stride) g_sums[i] = 0.f;
    for (int i = t; i < NG; i += stride) g_cnt[i] = 0.f;
}

__global__ void k_deg(const int* __restrict__ dst) {
    int t = blockIdx.x * blockDim.x + threadIdx.x;
    if (t < NE) atomicAdd(&g_cnti[dst[t]], 1);
}

// init: x16 = f16(x) zero-padded to 80; agg1 = f16(x/deg); dinv/inv per node;
// also the per-graph node count (fused former k_cnt).
__global__ void k_init1(const float* __restrict__ x,
                        const int* __restrict__ batch) {
    int t = blockIdx.x * blockDim.x + threadIdx.x;
    if (t < NN * 10) {
        int i = t / 10;
        int q = t - i * 10;
        float d = (float)g_cnti[i] + 1.0f;
        float inv = 1.0f / d;
        if (q == 0) {
            g_dinv[i] = rsqrtf(d);
            g_inv[i] = inv;
            atomicAdd(&g_cnt[batch[i]], 1.0f);
        }
        float v[8];
        if (q < 9) {
            const float2* xp = (const float2*)(x + (long)i * 78 + q * 8);
#pragma unroll
            for (int j = 0; j < 4; j++) {
                float2 a = xp[j];
                v[2 * j] = a.x; v[2 * j + 1] = a.y;
            }
        } else {
            const float2* xp = (const float2*)(x + (long)i * 78 + 72);
#pragma unroll
            for (int j = 0; j < 3; j++) {
                float2 a = xp[j];
                v[2 * j] = a.x; v[2 * j + 1] = a.y;
            }
            v[6] = 0.f; v[7] = 0.f;
        }
        uint4 raw, agg;
        __half2* rp = (__half2*)&raw;
        __half2* ap = (__half2*)&agg;
#pragma unroll
        for (int j = 0; j < 4; j++) {
            rp[j] = __floats2half2_rn(v[2 * j], v[2 * j + 1]);
            ap[j] = __floats2half2_rn(v[2 * j] * inv, v[2 * j + 1] * inv);
        }
        g_x16v[(long)i * 10 + q] = raw;
        g_agg1v[(long)i * 10 + q] = agg;
    }
}

// convert weights to f16 (W1 padded to 80 rows; fc1/fc2 too)
__global__ void k_wconv(const float* __restrict__ W1,
                        const float* __restrict__ W2,
                        const float* __restrict__ fc1_w,
                        const float* __restrict__ fc2_w) {
    int t = blockIdx.x * blockDim.x + threadIdx.x;
    if (t < 80 * 128) {
        int k = t >> 7;
        g_w1h[t] = __float2half((k < 78) ? W1[t] : 0.f);
    }
    if (t < 128 * 256) {
        g_w2h[t] = __float2half(W2[t]);
    }
    if (t < 320 * 512) {
        g_fc1h[t] = __float2half(fc1_w[t]);
    }
    if (t < 512) {
        g_fc2h[t] = __float2half(fc2_w[t]);
    }
}

// ---------------- edge scatter, layer 1 (f16, flat chunk space) -------------
__global__ void k_scatter1(const int* __restrict__ src,
                           const int* __restrict__ dst) {
    const int W = 2048 * 8;                 // total warps
    const int EPW = (NE + W - 1) / W;       // 98 edges per warp
    int w = (blockIdx.x * blockDim.x + threadIdx.x) >> 5;
    int lane = threadIdx.x & 31;
    int e0 = w * EPW;
    if (e0 >= NE) return;
    int ecnt = min(EPW, NE - e0);
    int nchunk = ecnt * 10;
    __half* agg = (__half*)g_agg1v;

    int c = lane;
    for (; c + 32 < nchunk; c += 64) {
        int c0 = c, c1 = c + 32;
        int le0 = c0 / 10, q0 = c0 - le0 * 10;
        int le1 = c1 / 10, q1 = c1 - le1 * 10;
        int e0i = e0 + le0, e1i = e0 + le1;
        int s0 = __ldg(src + e0i), d0 = __ldg(dst + e0i);
        int s1 = __ldg(src + e1i), d1 = __ldg(dst + e1i);
        float n0 = __ldg(g_dinv + s0) * __ldg(g_dinv + d0);
        float n1 = __ldg(g_dinv + s1) * __ldg(g_dinv + d1);
        uint4 v0 = g_x16v[(long)s0 * 10 + q0];
        uint4 v1 = g_x16v[(long)s1 * 10 + q1];
        red_f16x8(agg + (long)d0 * 80 + q0 * 8, v0, __float2half2_rn(n0));
        red_f16x8(agg + (long)d1 * 80 + q1 * 8, v1, __float2half2_rn(n1));
    }
    for (; c < nchunk; c += 32) {
        int le = c / 10, q = c - le * 10;
        int e = e0 + le;
        int s = __ldg(src + e), d = __ldg(dst + e);
        float nrm = __ldg(g_dinv + s) * __ldg(g_dinv + d);
        uint4 v = g_x16v[(long)s * 10 + q];
        red_f16x8(agg + (long)d * 80 + q * 8, v, __float2half2_rn(nrm));
    }
}

// ---------------- GEMM1 (tensor cores): h1=relu(agg1@W1+b1) (fp8); agg2=h1/deg (f16)
__global__ __launch_bounds__(256) void k_gemm1(const float* __restrict__ b1) {
    __shared__ union {
        struct {
            uint4 a[128 * 11];   // f16 [128][88]
            uint4 b[80 * 17];    // f16 [80][136]
        } ld;
        float stg[128 * 68];
    } sm;
    int tid = threadIdx.x;
    int r0 = blockIdx.x * 128;
    int wid = tid >> 5;
    int wm = wid >> 1;      // 0..3
    int wn = wid & 1;       // 0..1

    const uint4 zero4 = make_uint4(0, 0, 0, 0);
    for (int idx = tid; idx < 128 * 10; idx += 256) {
        int r = idx / 10, u = idx - r * 10;
        int row = r0 + r;
        sm.ld.a[r * 11 + u] = (row < NN) ? g_agg1v[(long)row * 10 + u] : zero4;
    }
    const uint4* w1v = (const uint4*)g_w1h;
    for (int idx = tid; idx < 80 * 16; idx += 256) {
        int k = idx >> 4, u = idx & 15;
        sm.ld.b[k * 17 + u] = w1v[k * 16 + u];
    }
    __syncthreads();

    wmma::fragment<wmma::accumulator, 16, 16, 16, float> cf[2][4];
#pragma unroll
    for (int i = 0; i < 2; i++)
#pragma unroll
        for (int j = 0; j < 4; j++) wmma::fill_fragment(cf[i][j], 0.f);

    const __half* As = (const __half*)sm.ld.a;
    const __half* Bs = (const __half*)sm.ld.b;
#pragma unroll
    for (int k = 0; k < 80; k += 16) {
        wmma::fragment<wmma::matrix_a, 16, 16, 16, __half, wmma::row_major> af[2];
        wmma::load_matrix_sync(af[0], As + (wm * 32) * 88 + k, 88);
        wmma::load_matrix_sync(af[1], As + (wm * 32 + 16) * 88 + k, 88);
        wmma::fragment<wmma::matrix_b, 16, 16, 16, __half, wmma::row_major> bf[4];
#pragma unroll
        for (int j = 0; j < 4; j++)
            wmma::load_matrix_sync(bf[j], Bs + k * 136 + wn * 64 + j * 16, 136);
#pragma unroll
        for (int i = 0; i < 2; i++)
#pragma unroll
            for (int j = 0; j < 4; j++)
                wmma::mma_sync(cf[i][j], af[i], bf[j], cf[i][j]);
    }
    __syncthreads();

    unsigned short* h1q = (unsigned short*)g_h1qv;
    __half* a2 = (__half*)g_agg2v;
#pragma unroll 1
    for (int ph = 0; ph < 2; ph++) {
        if (wn == ph) {
#pragma unroll
            for (int i = 0; i < 2; i++)
#pragma unroll
                for (int j = 0; j < 4; j++)
                    wmma::store_matrix_sync(
                        sm.stg + (wm * 32 + i * 16) * 68 + j * 16,
                        cf[i][j], 68, wmma::mem_row_major);
        }
        __syncthreads();
        for (int idx = tid; idx < 128 * 32; idx += 256) {
            int r = idx >> 5;
            int cp = idx & 31;
            int row = r0 + r;
            if (row < NN) {
                int col = ph * 64 + cp * 2;          // global column
                float v0 = sm.stg[r * 68 + cp * 2];  // local read
                float v1 = sm.stg[r * 68 + cp * 2 + 1];
                v0 = fmaxf(v0 + b1[col], 0.f);
                v1 = fmaxf(v1 + b1[col + 1], 0.f);
                float inv = __ldg(g_inv + row);
                __nv_fp8x2_e4m3 q2(make_float2(v0, v1));
                h1q[(long)row * 64 + (col >> 1)] = (unsigned short)q2.__x;
                *(__half2*)(a2 + (long)row * 128 + col) =
                    __floats2half2_rn(v0 * inv, v1 * inv);
            }
        }
        __syncthreads();
    }
}

// ---------------- edge scatter, layer 2 (fp8 read, f16 RED) -----------------
// 128 fp8 = 128 B per row = 16 x uint2; lanes 0-15 edge e, 16-31 edge e+1.
__global__ void k_scatter2(const int* __restrict__ src,
                           const int* __restrict__ dst) {
    const int W = 2048 * 8;
    const int EPW = (NE + W - 1) / W;       // 98
    int w = (blockIdx.x * blockDim.x + threadIdx.x) >> 5;
    int lane = threadIdx.x & 31;
    int half = lane >> 4;
    int q = lane & 15;
    int e = w * EPW;
    int end = min(e + EPW, NE);
    if (e >= NE) return;
    __half* agg = (__half*)g_agg2v;

    for (; e + 3 < end; e += 4) {
        int ea = e + half, eb = e + 2 + half;
        int sa = __ldg(src + ea), da = __ldg(dst + ea);
        int sb = __ldg(src + eb), db = __ldg(dst + eb);
        float na = __ldg(g_dinv + sa) * __ldg(g_dinv + da);
        float nb = __ldg(g_dinv + sb) * __ldg(g_dinv + db);
        uint2 qa = g_h1qv[(long)sa * 16 + q];
        uint2 qb = g_h1qv[(long)sb * 16 + q];
        uint4 va = fp8x8_to_f16x8(qa);
        uint4 vb = fp8x8_to_f16x8(qb);
        red_f16x8(agg + (long)da * 128 + q * 8, va, __float2half2_rn(na));
        red_f16x8(agg + (long)db * 128 + q * 8, vb, __float2half2_rn(nb));
    }
    for (; e < end; e += 2) {
        if (e + half < end) {
            int ei = e + half;
            int s = __ldg(src + ei), d = __ldg(dst + ei);
            float nrm = __ldg(g_dinv + s) * __ldg(g_dinv + d);
            uint2 qv = g_h1qv[(long)s * 16 + q];
            uint4 v = fp8x8_to_f16x8(qv);
            red_f16x8(agg + (long)d * 128 + q * 8, v, __float2half2_rn(nrm));
        }
    }
}

// ---------------- GEMM2 (tensor cores) + fused mean-pool epilogue -----------
__global__ __launch_bounds__(256) void k_gemm2(const float* __restrict__ b2,
                                               const int* __restrict__ batch) {
    __shared__ union {
        struct {
            uint4 a[128 * 9];    // f16 [128][72] (K chunk 64)
            uint4 b[64 * 17];    // f16 [64][136]
        } ld;
        float stg[128 * 68];
    } sm;
    int tid = threadIdx.x;
    int r0 = blockIdx.x * 128;
    int cb = blockIdx.y * 128;
    int wid = tid >> 5;
    int wm = wid >> 1;
    int wn = wid & 1;

    wmma::fragment<wmma::accumulator, 16, 16, 16, float> cf[2][4];
#pragma unroll
    for (int i = 0; i < 2; i++)
#pragma unroll
        for (int j = 0; j < 4; j++) wmma::fill_fragment(cf[i][j], 0.f);

    const uint4 zero4 = make_uint4(0, 0, 0, 0);
    const uint4* w2v = (const uint4*)g_w2h;   // rows of 32 uint4 (256 halves)
    const __half* As = (const __half*)sm.ld.a;
    const __half* Bs = (const __half*)sm.ld.b;

#pragma unroll 1
    for (int kc = 0; kc < 128; kc += 64) {
        __syncthreads();
        for (int idx = tid; idx < 128 * 8; idx += 256) {
            int r = idx >> 3, u = idx & 7;
            int row = r0 + r;
            sm.ld.a[r * 9 + u] =
                (row < NN) ? g_agg2v[(long)row * 16 + (kc >> 3) + u] : zero4;
        }
        for (int idx = tid; idx < 64 * 16; idx += 256) {
            int k = idx >> 4, u = idx & 15;
            sm.ld.b[k * 17 + u] = w2v[(kc + k) * 32 + (cb >> 3) + u];
        }
        __syncthreads();
#pragma unroll
        for (int k = 0; k < 64; k += 16) {
            wmma::fragment<wmma::matrix_a, 16, 16, 16, __half, wmma::row_major> af[2];
            wmma::load_matrix_sync(af[0], As + (wm * 32) * 72 + k, 72);
            wmma::load_matrix_sync(af[1], As + (wm * 32 + 16) * 72 + k, 72);
            wmma::fragment<wmma::matrix_b, 16, 16, 16, __half, wmma::row_major> bf[4];
#pragma unroll
            for (int j = 0; j < 4; j++)
                wmma::load_matrix_sync(bf[j], Bs + k * 136 + wn * 64 + j * 16, 136);
#pragma unroll
            for (int i = 0; i < 2; i++)
#pragma unroll
                for (int j = 0; j < 4; j++)
                    wmma::mma_sync(cf[i][j], af[i], bf[j], cf[i][j]);
        }
    }
    __syncthreads();

#pragma unroll 1
    for (int ph = 0; ph < 2; ph++) {
        if (wn == ph) {
#pragma unroll
            for (int i = 0; i < 2; i++)
#pragma unroll
                for (int j = 0; j < 4; j++)
                    wmma::store_matrix_sync(
                        sm.stg + (wm * 32 + i * 16) * 68 + j * 16,
                        cf[i][j], 68, wmma::mem_row_major);
        }
        __syncthreads();
        for (int idx = tid; idx < 128 * 16; idx += 256) {
            int r = idx >> 4;
            int qd = idx & 15;
            int row = r0 + r;
            if (row < NN) {
                int lcol = qd * 4;                   // local staged column
                int gcol = cb + ph * 64 + lcol;      // global output column
                float v0 = fmaxf(sm.stg[r * 68 + lcol + 0] + b2[gcol + 0], 0.f);
                float v1 = fmaxf(sm.stg[r * 68 + lcol + 1] + b2[gcol + 1], 0.f);
                float v2 = fmaxf(sm.stg[r * 68 + lcol + 2] + b2[gcol + 2], 0.f);
                float v3 = fmaxf(sm.stg[r * 68 + lcol + 3] + b2[gcol + 3], 0.f);
                int g = __ldg(batch + row);
                float* p = g_sums + g * 256 + gcol;
                asm volatile("red.global.add.v4.f32 [%0], {%1,%2,%3,%4};"
                             :: "l"(p), "f"(v0), "f"(v1), "f"(v2), "f"(v3)
                             : "memory");
            }
        }
        __syncthreads();
    }
}

// ---------------- protein path -----------------------------------------------
__global__ void k_ptable(const float* __restrict__ emb,
                         const float* __restrict__ conv_w) {
    int idx = blockIdx.x * blockDim.x + threadIdx.x;
    if (idx < 25 * 8 * 64) {
        int o = idx & 63;
        int k = (idx >> 6) & 7;
        int tok = idx >> 9;
        float s = 0.f;
#pragma unroll 4
        for (int i = 0; i < 128; i++)
            s += emb[tok * 128 + i] * conv_w[o * 1024 + i * 8 + k];
        g_ptab[tok * 512 + k * 64 + o] = s;
    }
}

__global__ __launch_bounds__(256) void k_conv(const int* __restrict__ seq,
                                              const float* __restrict__ conv_b) {
    __shared__ float2 stab[25 * 8 * 16];   // [tok][k][chan-pair]
    __shared__ int sseq[1024];
    __shared__ float2 sred[256];
    int tid = threadIdx.x;
    int b = blockIdx.x;
    int co = blockIdx.y * 32;

    for (int idx = tid; idx < 1024; idx += 256) sseq[idx] = seq[b * 1024 + idx];
    for (int idx = tid; idx < 25 * 8 * 16; idx += 256) {
        int p = idx & 15;
        int kk = (idx >> 4) & 7;
        int tok = idx >> 7;
        stab[idx] = make_float2(g_ptab[tok * 512 + kk * 64 + co + 2 * p],
                                g_ptab[tok * 512 + kk * 64 + co + 2 * p + 1]);
    }
    __syncthreads();

    int p = tid & 15;
    int phase = tid >> 4;
    float2 m = make_float2(-1e30f, -1e30f);
    for (int l = phase; l < 1017; l += 16) {
        float sx = 0.f, sy = 0.f;
#pragma unroll
        for (int k = 0; k < 8; k++) {
            float2 v = stab[(sseq[l + k] * 8 + k) * 16 + p];
            sx += v.x; sy += v.y;
        }
        m.x = fmaxf(m.x, sx);
        m.y = fmaxf(m.y, sy);
    }
    sred[tid] = m;
    __syncthreads();
    if (tid < 16) {
        float2 mm = sred[tid];
#pragma unroll
        for (int g = 1; g < 16; g++) {
            float2 v = sred[g * 16 + tid];
            mm.x = fmaxf(mm.x, v.x);
            mm.y = fmaxf(mm.y, v.y);
        }
        g_prot[b * 64 + co + 2 * tid]     = fmaxf(mm.x + conv_b[co + 2 * tid], 0.f);
        g_prot[b * 64 + co + 2 * tid + 1] = fmaxf(mm.y + conv_b[co + 2 * tid + 1], 0.f);
    }
}

// ---------------- final MLP (f16 weights) -------------------------------------
__global__ __launch_bounds__(256) void k_final(const float* __restrict__ fc1_b,
                                               const float* __restrict__ fc2_b,
                                               float* __restrict__ out) {
    __shared__ float comb[320];
    __shared__ float sred[256];
    int tid = threadIdx.x;
    int b = blockIdx.x;
    float invc = 1.0f / fmaxf(g_cnt[b], 1.0f);
    if (tid < 256) comb[tid] = g_sums[b * 256 + tid] * invc;
    if (tid < 64) comb[256 + tid] = g_prot[b * 64 + tid];
    __syncthreads();

    float part = 0.f;
#pragma unroll
    for (int rep = 0; rep < 2; rep++) {
        int o = tid + rep * 256;
        float acc = fc1_b[o];
#pragma unroll 4
        for (int j = 0; j < 320; j++)
            acc += comb[j] * __half2float(g_fc1h[j * 512 + o]);
        part += fmaxf(acc, 0.f) * __half2float(g_fc2h[o]);
    }
    sred[tid] = part;
    __syncthreads();
    for (int s = 128; s > 0; s >>= 1) {
        if (tid < s) sred[tid] += sred[tid + s];
        __syncthreads();
    }
    if (tid == 0) out[b] = sred[0] + fc2_b[0];
}

// ---------------- launch ------------------------------------------------------
extern "C" void kernel_launch(void* const* d_in, const int* in_sizes, int n_in,
                              void* d_out, int out_size) {
    const float* x       = (const float*)d_in[0];
    const int*   ei      = (const int*)  d_in[1];   // [2, NE]
    const int*   batch   = (const int*)  d_in[2];
    const int*   seq     = (const int*)  d_in[3];   // [NG, 1024]
    const float* W1      = (const float*)d_in[4];
    const float* b1      = (const float*)d_in[5];
    const float* W2      = (const float*)d_in[6];
    const float* b2      = (const float*)d_in[7];
    const float* emb     = (const float*)d_in[8];
    const float* conv_w  = (const float*)d_in[9];
    const float* conv_b  = (const float*)d_in[10];
    const float* fc1_w   = (const float*)d_in[11];
    const float* fc1_b   = (const float*)d_in[12];
    const float* fc2_w   = (const float*)d_in[13];
    const float* fc2_b   = (const float*)d_in[14];
    float* out = (float*)d_out;

    const int* src = ei;
    const int* dst = ei + NE;

    k_zero<<<512, 256>>>();                                   // 1
    k_deg<<<(NE + 255) / 256, 256>>>(dst);                    // 2
    k_init1<<<(NN * 10 + 255) / 256, 256>>>(x, batch);        // 3
    k_scatter1<<<2048, 256>>>(src, dst);                      // 4  <- profiled
    k_wconv<<<(320 * 512 + 255) / 256, 256>>>(W1, W2, fc1_w, fc2_w); // 5
    k_gemm1<<<(NN + 127) / 128, 256>>>(b1);                   // 6
    k_scatter2<<<2048, 256>>>(src, dst);                      // 7
    {
        dim3 grid((NN + 127) / 128, 2);
        k_gemm2<<<grid, 256>>>(b2, batch);                    // 8
    }
    k_ptable<<<(25 * 8 * 64 + 255) / 256, 256>>>(emb, conv_w);// 9
    {
        dim3 grid(NG, 2);
        k_conv<<<grid, 256>>>(seq, conv_b);                   // 10
    }
    k_final<<<NG, 256>>>(fc1_b, fc2_b, out);                  // 11
}